// round 14
// baseline (speedup 1.0000x reference)
#include <cuda_runtime.h>
#include <cstdint>

// ---------------- problem constants ----------------
#define E       256
#define NB      4
#define NTOK    3136            // 16 * 14 * 14
#define MTOT    (NB*NTOK)       // 12544
#define KCONV   2304            // 3 * 3 * 16 * 16
#define NCHUNK  (KCONV/16)      // 144
#define THRESH  1.5f
#define R       32              // rows per block
#define NBLK    (MTOT/R)        // 392

typedef unsigned long long ull;

// ---------------- device scratch ----------------
__device__ float g_wTconv[KCONV*E];     // conv weights transposed [k][oc]
__device__ float g_wT[7][E*E];          // 0:wk 1:wv 2:Wki 3:Wvi 4:outproj 5:dense 6:bproj  [k][n]
__device__ float g_q0add[E];
__device__ float g_vp[MTOT*E];
__device__ float g_attn[MTOT*E];
__device__ float g_bytemean[NTOK];
__device__ float g_scores[NTOK*NB*4];   // [n][b][h]
__device__ int   g_boundary[NTOK];
__device__ int   g_segstart[NTOK+2];
__device__ int   g_nseg;
__device__ float g_qp[E];

// ---------------- helpers ----------------
#define DUP(d,f)      asm("mov.b64 %0,{%1,%1};" : "=l"(d) : "f"(f))
#define FMA2(a_,b_,c_) asm("fma.rn.f32x2 %0, %1, %2, %0;" : "+l"(c_) : "l"(a_), "l"(b_))
#define SEL(v,kk) ((kk)==0?(v).x:(kk)==1?(v).y:(kk)==2?(v).z:(v).w)

__device__ __forceinline__ float2 unpack2(ull v){
    float2 r;
    r.x = __uint_as_float((unsigned)(v & 0xffffffffull));
    r.y = __uint_as_float((unsigned)(v >> 32));
    return r;
}

__device__ __forceinline__ float warpSum(float v){
    #pragma unroll
    for(int o=16;o;o>>=1) v += __shfl_xor_sync(0xffffffffu, v, o);
    return v;
}

__device__ __forceinline__ float blockReduceSum(float v, float* red){
    v = warpSum(v);
    int w = threadIdx.x >> 5, l = threadIdx.x & 31;
    if(l==0) red[w] = v;
    __syncthreads();
    if(w==0){
        float x = (l < 8) ? red[l] : 0.f;
        #pragma unroll
        for(int o=4;o;o>>=1) x += __shfl_xor_sync(0xffffffffu, x, o);
        if(l==0) red[8] = x;
    }
    __syncthreads();
    float r = red[8];
    __syncthreads();
    return r;
}

__device__ __forceinline__ float blockReduceMax(float v, float* red){
    #pragma unroll
    for(int o=16;o;o>>=1) v = fmaxf(v, __shfl_xor_sync(0xffffffffu, v, o));
    int w = threadIdx.x >> 5, l = threadIdx.x & 31;
    if(l==0) red[w] = v;
    __syncthreads();
    if(w==0){
        float x = (l < 8) ? red[l] : -3.402823466e38f;
        #pragma unroll
        for(int o=4;o;o>>=1) x = fmaxf(x, __shfl_xor_sync(0xffffffffu, x, o));
        if(l==0) red[8] = x;
    }
    __syncthreads();
    float r = red[8];
    __syncthreads();
    return r;
}

// ---------------- 16-k inner step: warp = 8 rows x 128 cols, B DIRECT FROM GLOBAL ----------------
// Bcol = weight base + column offset (chalf*128 + lane*4); row stride 256; L1-resident after warmup
template<int ASTR>
__device__ __forceinline__ void mm16g(const float* __restrict__ Ar, const float* __restrict__ Bcol,
                                      int kbase, ull acc[8][2]){
    #pragma unroll
    for(int kg=0;kg<16;kg+=4){
        ulonglong2 q[4];
        #pragma unroll
        for(int kk=0;kk<4;kk++)
            q[kk] = *(const ulonglong2*)&Bcol[(size_t)(kbase+kg+kk)*256];
        float4 a[8];
        #pragma unroll
        for(int r=0;r<8;r++) a[r] = *(const float4*)&Ar[r*ASTR + kbase + kg];
        #pragma unroll
        for(int kk=0;kk<4;kk++){
            #pragma unroll
            for(int r=0;r<8;r++){
                ull ad; DUP(ad, SEL(a[r],kk));
                FMA2(ad, q[kk].x, acc[r][0]);
                FMA2(ad, q[kk].y, acc[r][1]);
            }
        }
    }
}

// C_block[32x256] = A_smem[32x256] @ Bg[256x256 (k-major, global)]
// NO barriers inside the k-loop; warps free-run
__device__ __forceinline__ void gemm256(const float* __restrict__ A, const float* __restrict__ Bg,
                                        ull acc[8][2], int tid){
    int w = tid>>5, lane = tid&31;
    int wr = w & 3, chalf = w >> 2;
    const float* Ar = A + (wr*8)*256;
    const float* Bcol = Bg + chalf*128 + lane*4;
    #pragma unroll
    for(int i=0;i<8;i++){ acc[i][0]=0ull; acc[i][1]=0ull; }

    __syncthreads();   // A source smem ready (written by prior epilogue)

    #pragma unroll 1
    for(int kb=0;kb<256;kb+=16)
        mm16g<256>(Ar, Bcol, kb, acc);
}

// bias + LN row-wise (row spans 2 warps) -> smem C (stride 256)
__device__ __forceinline__ void ln_epilogue(ull acc[8][2], const float* __restrict__ bias,
        const float* __restrict__ g, const float* __restrict__ b, float* __restrict__ C,
        int wr, int chalf, int lane, float (*redS)[32][2]){
    int c0 = chalf*128 + lane*4;
    float x[8][4];
    #pragma unroll
    for(int i=0;i<8;i++){
        float2 r0 = unpack2(acc[i][0]), r1 = unpack2(acc[i][1]);
        x[i][0] = r0.x + bias[c0];   x[i][1] = r0.y + bias[c0+1];
        x[i][2] = r1.x + bias[c0+2]; x[i][3] = r1.y + bias[c0+3];
        float s = warpSum(x[i][0]+x[i][1]+x[i][2]+x[i][3]);
        if(lane==0) redS[0][wr*8+i][chalf] = s;
    }
    __syncthreads();
    float mean[8];
    #pragma unroll
    for(int i=0;i<8;i++)
        mean[i] = (redS[0][wr*8+i][0] + redS[0][wr*8+i][1]) * (1.f/256.f);
    #pragma unroll
    for(int i=0;i<8;i++){
        float vs = 0.f;
        #pragma unroll
        for(int j=0;j<4;j++){ float d = x[i][j]-mean[i]; vs += d*d; }
        vs = warpSum(vs);
        if(lane==0) redS[1][wr*8+i][chalf] = vs;
    }
    __syncthreads();
    #pragma unroll
    for(int i=0;i<8;i++){
        float var = (redS[1][wr*8+i][0] + redS[1][wr*8+i][1]) * (1.f/256.f);
        float inv = rsqrtf(var + 1e-5f);
        float4 y;
        y.x = (x[i][0]-mean[i])*inv*g[c0]   + b[c0];
        y.y = (x[i][1]-mean[i])*inv*g[c0+1] + b[c0+1];
        y.z = (x[i][2]-mean[i])*inv*g[c0+2] + b[c0+2];
        y.w = (x[i][3]-mean[i])*inv*g[c0+3] + b[c0+3];
        *(float4*)&C[(wr*8+i)*256 + c0] = y;
    }
    __syncwarp();
}

__device__ __forceinline__ void store_bias_global(ull acc[8][2], const float* __restrict__ bias,
        float* __restrict__ dst, int wr, int chalf, int lane){
    int c0 = chalf*128 + lane*4;
    #pragma unroll
    for(int i=0;i<8;i++){
        float2 r0 = unpack2(acc[i][0]), r1 = unpack2(acc[i][1]);
        float4 y = { r0.x + bias[c0], r0.y + bias[c0+1], r1.x + bias[c0+2], r1.y + bias[c0+3] };
        *(float4*)&dst[(size_t)(wr*8+i)*E + c0] = y;
    }
}

// kp epilogue: scores directly; head (64 cols) fully inside this warp's 128-col half
__device__ __forceinline__ void score_epilogue(ull acc[8][2], const float* __restrict__ bias,
        int m0, int wr, int chalf, int lane){
    int c0 = chalf*128 + lane*4;
    int head = chalf*2 + (lane>>4);
    #pragma unroll
    for(int i=0;i<8;i++){
        float2 r0 = unpack2(acc[i][0]), r1 = unpack2(acc[i][1]);
        float s = (r0.x + bias[c0]  )*g_qp[c0]   + (r0.y + bias[c0+1])*g_qp[c0+1]
                + (r1.x + bias[c0+2])*g_qp[c0+2] + (r1.y + bias[c0+3])*g_qp[c0+3];
        #pragma unroll
        for(int o=8;o;o>>=1) s += __shfl_xor_sync(0xffffffffu, s, o);
        if((lane & 15) == 0){
            int m = m0 + wr*8 + i;
            int b = m / NTOK, n = m % NTOK;
            g_scores[n*16 + b*4 + head] = s;
        }
    }
}

// ---------------- prep ----------------
__global__ void prep_conv_kernel(const float* __restrict__ conv_w){
    __shared__ float t[32][33];
    int kk0 = blockIdx.x*32, oc0 = blockIdx.y*32;
    int tx = threadIdx.x, ty = threadIdx.y;   // 32 x 8
    #pragma unroll
    for(int p=0;p<4;p++)
        t[ty + p*8][tx] = conv_w[(size_t)(oc0 + ty + p*8)*KCONV + kk0 + tx];
    __syncthreads();
    #pragma unroll
    for(int p=0;p<4;p++)
        g_wTconv[(size_t)(kk0 + ty + p*8)*E + oc0 + tx] = t[tx][ty + p*8];
}

__global__ void prep_kernel(const float* __restrict__ wk, const float* __restrict__ wv,
                            const float* __restrict__ ipw,
                            const float* __restrict__ outp, const float* __restrict__ dense,
                            const float* __restrict__ bproj, const float* __restrict__ gq){
    int idx = blockIdx.x*blockDim.x + threadIdx.x;
    int stride = gridDim.x*blockDim.x;
    for(int i=idx;i<E*E;i+=stride){
        int k = i >> 8, n = i & 255;
        g_wT[0][i] = wk[n*E + k];
        g_wT[1][i] = wv[n*E + k];
        g_wT[2][i] = ipw[(E   + n)*E + k];
        g_wT[3][i] = ipw[(2*E + n)*E + k];
        g_wT[4][i] = outp[n*E + k];
        g_wT[5][i] = dense[n*E + k];
        g_wT[6][i] = bproj[n*E + k];
    }
    for(int i=idx;i<E;i+=stride) g_q0add[i] = gq[i];
}

// ---------------- fused conv + k/v chain ----------------
// smem floats: T[0,8192) C[8192,16384) ; conv As ping-pong (2 x 640) lives in C region
#define SMEM_BIG_FLOATS 16384

__global__ __launch_bounds__(256,2) void conv_kv_kernel(const float* __restrict__ video,
        const float* __restrict__ conv_b,
        const float* __restrict__ wk_b, const float* __restrict__ wv_b,
        const float* __restrict__ ipb,
        const float* __restrict__ lnk_g, const float* __restrict__ lnk_b,
        const float* __restrict__ lnv_g, const float* __restrict__ lnv_b){
    extern __shared__ float sm[];
    __shared__ float redS[2][32][2];
    float* T   = sm;
    float* C   = sm + 8192;
    float* As  = C;              // 2 x 640 ping-pong during conv
    int tid = threadIdx.x;
    int w = tid>>5, lane = tid&31;
    int wr = w & 3, chalf = w >> 2;
    int m0 = blockIdx.x*R;

    // gather coords: row = tid>>3, q = tid&7 -> kw pair (2q, 2q+1)
    int rowA = tid >> 3, qA = tid & 7;
    int mA = m0 + rowA;
    int bA = mA / NTOK; int nA = mA % NTOK;
    int dA = nA / 196;  int hA = (nA % 196) / 14; int wA = nA % 14;
    const float* vbase = video + (size_t)(bA*3)*32*50176 + (hA*16)*224 + wA*16 + qA*2;
    int dbase = 2*dA - 1;

    const float* Bconv = g_wTconv + chalf*128 + lane*4;

    ull acc[8][2];
    #pragma unroll
    for(int i=0;i<8;i++){ acc[i][0]=0ull; acc[i][1]=0ull; }

    #define GATHER_A(ci, dst) { int kb_=(ci)*16; int c_=kb_/768, rem_=kb_%768;           \
        int kd_=rem_>>8, kh_=(rem_&255)>>4; int din_=dbase+kd_;                           \
        dst = make_float2(0.f, 0.f);                                                      \
        if(din_>=0 && din_<32) dst = *(const float2*)(vbase + (size_t)(c_*32+din_)*50176 + kh_*224); }

    float2 apre;
    GATHER_A(0, apre);
    *(float2*)&As[rowA*20 + qA*2] = apre;
    GATHER_A(1, apre);
    __syncthreads();

    #pragma unroll 1
    for(int ci=0; ci<NCHUNK; ci++){
        int cur = ci & 1;
        if(ci < NCHUNK-1){
            float* an = As + (cur^1)*640;
            *(float2*)&an[rowA*20 + qA*2] = apre;
        }
        if(ci < NCHUNK-2){
            GATHER_A(ci+2, apre);
        }
        mm16g<20>(As + cur*640 + (wr*8)*20, Bconv + (size_t)ci*16*256, 0, acc);
        __syncthreads();
    }

    // conv epilogue: bias + relu -> T; cross-warp row sums for byte path
    {
        int c0 = chalf*128 + lane*4;
        #pragma unroll
        for(int i=0;i<8;i++){
            float2 r0 = unpack2(acc[i][0]), r1 = unpack2(acc[i][1]);
            float4 y = { fmaxf(r0.x + conv_b[c0],  0.f), fmaxf(r0.y + conv_b[c0+1],0.f),
                         fmaxf(r1.x + conv_b[c0+2],0.f), fmaxf(r1.y + conv_b[c0+3],0.f) };
            *(float4*)&T[(wr*8+i)*256 + c0] = y;
            float s = warpSum(y.x + y.y + y.z + y.w);
            if(lane==0) redS[0][wr*8+i][chalf] = s;
        }
        __syncthreads();
        if(m0 < NTOK && tid < 32)
            g_bytemean[m0 + tid] = (redS[0][tid][0] + redS[0][tid][1]) * (1.f/256.f);
    }

    // k path: k = LN(T@wk + b) ; scores from kp = k@Wki + b (kp stays in regs)
    gemm256(T, g_wT[0], acc, tid);
    ln_epilogue(acc, wk_b, lnk_g, lnk_b, C, wr, chalf, lane, redS);
    gemm256(C, g_wT[2], acc, tid);
    score_epilogue(acc, ipb + E, m0, wr, chalf, lane);

    // v path
    gemm256(T, g_wT[1], acc, tid);
    ln_epilogue(acc, wv_b, lnv_g, lnv_b, C, wr, chalf, lane, redS);
    gemm256(C, g_wT[3], acc, tid);
    store_bias_global(acc, ipb + 2*E, g_vp + (size_t)m0*E, wr, chalf, lane);
}

// ---------------- fused out_proj -> dense -> bproj ----------------
__global__ __launch_bounds__(256,2) void out_chain_kernel(const float* __restrict__ outp_b,
        const float* __restrict__ dense_b, const float* __restrict__ bproj_b,
        float* __restrict__ out){
    extern __shared__ float sm[];
    float* T   = sm;
    float* C   = sm + 8192;
    int tid = threadIdx.x;
    int w = tid>>5, lane = tid&31;
    int wr = w & 3, chalf = w >> 2;
    int m0 = blockIdx.x*R;
    int c0 = chalf*128 + lane*4;

    #pragma unroll
    for(int p=0;p<8;p++){
        int fid = tid + p*256;
        int r = fid>>6, c4 = (fid&63)<<2;
        *(float4*)&T[r*256 + c4] = *(const float4*)&g_attn[(size_t)(m0+r)*E + c4];
    }
    // gemm256's entry barrier orders these writes before reads

    ull acc[8][2];

    gemm256(T, g_wT[4], acc, tid);      // attn @ out_proj
    #pragma unroll
    for(int i=0;i<8;i++){
        float2 r0 = unpack2(acc[i][0]), r1 = unpack2(acc[i][1]);
        float4 y = { r0.x + outp_b[c0], r0.y + outp_b[c0+1], r1.x + outp_b[c0+2], r1.y + outp_b[c0+3] };
        *(float4*)&C[(wr*8+i)*256 + c0] = y;
    }
    __syncwarp();

    gemm256(C, g_wT[5], acc, tid);      // @ dense + bias + q0
    #pragma unroll
    for(int i=0;i<8;i++){
        float2 r0 = unpack2(acc[i][0]), r1 = unpack2(acc[i][1]);
        float4 y = { r0.x + dense_b[c0]   + g_q0add[c0],
                     r0.y + dense_b[c0+1] + g_q0add[c0+1],
                     r1.x + dense_b[c0+2] + g_q0add[c0+2],
                     r1.y + dense_b[c0+3] + g_q0add[c0+3] };
        *(float4*)&T[(wr*8+i)*256 + c0] = y;
    }
    __syncwarp();

    gemm256(T, g_wT[6], acc, tid);      // @ bproj + bias, mask
    int nseg = g_nseg;
    #pragma unroll
    for(int i=0;i<8;i++){
        int m = m0 + wr*8 + i;
        int srow = m % NTOK;
        bool z = (srow >= nseg);
        float2 r0 = unpack2(acc[i][0]), r1 = unpack2(acc[i][1]);
        float4 y = { r0.x + bproj_b[c0], r0.y + bproj_b[c0+1], r1.x + bproj_b[c0+2], r1.y + bproj_b[c0+3] };
        if(z) y = make_float4(0.f,0.f,0.f,0.f);
        *(float4*)&out[(size_t)m*E + c0] = y;
    }
}

// ---------------- entropy -> boundary ----------------
__global__ void ent_kernel(const float* __restrict__ table){
    __shared__ float red[9];
    int n = blockIdx.x, c = threadIdx.x;
    float mean = g_bytemean[n];
    int byte = (int)rintf(mean * 255.f);
    byte = min(255, max(0, byte));
    float l = table[byte*256 + c];
    float mx = blockReduceMax(l, red);
    float e = expf(l - mx);
    float s = blockReduceSum(e, red);
    float p = e / s;
    float t = -p * log2f(p + 1e-9f);
    float ent = blockReduceSum(t, red);
    if(c == 0) g_boundary[n] = (ent > THRESH) ? 1 : 0;
}

// ---------------- prefix scan -> segment starts ----------------
__global__ void scan_kernel(){
    __shared__ int smi[1024];
    int tid = threadIdx.x;
    int base = tid*4;
    int v[4]; int sum = 0;
    #pragma unroll
    for(int i=0;i<4;i++){
        int idx = base + i;
        int bb = (idx < NTOK) ? g_boundary[idx] : 0;
        v[i] = sum; sum += bb;
    }
    smi[tid] = sum;
    __syncthreads();
    for(int off=1; off<1024; off<<=1){
        int t = (tid >= off) ? smi[tid-off] : 0;
        __syncthreads();
        smi[tid] += t;
        __syncthreads();
    }
    int prev = (tid > 0) ? smi[tid-1] : 0;
    if(tid == 0) g_segstart[0] = 0;
    #pragma unroll
    for(int i=0;i<4;i++){
        int idx = base + i;
        if(idx < NTOK){
            int sg = prev + v[i];
            if(g_boundary[idx]) g_segstart[sg + 1] = idx + 1;
            if(idx == NTOK-1){
                g_nseg = sg + 1;
                g_segstart[sg + 1] = NTOK;
            }
        }
    }
}

// ---------------- query path ----------------
__global__ void qp_kernel(const float* __restrict__ gq,
                          const float* __restrict__ wq_w, const float* __restrict__ wq_b,
                          const float* __restrict__ lnq_g, const float* __restrict__ lnq_b,
                          const float* __restrict__ ipw, const float* __restrict__ ipb){
    __shared__ float red[9];
    __shared__ float q0s[E];
    __shared__ float qln[E];
    int c = threadIdx.x;
    q0s[c] = gq[c];
    __syncthreads();
    float y = wq_b[c];
    for(int k=0;k<E;k++) y += wq_w[c*E + k]*q0s[k];
    float mean = blockReduceSum(y, red) * (1.f/E);
    float dd = y - mean;
    float var = blockReduceSum(dd*dd, red) * (1.f/E);
    qln[c] = dd * rsqrtf(var + 1e-5f) * lnq_g[c] + lnq_b[c];
    __syncthreads();
    float z = ipb[c];
    for(int k=0;k<E;k++) z += ipw[c*E + k]*qln[k];
    g_qp[c] = z * 0.125f;       // dh^-0.5
}

// ---------------- segment softmax-attention ----------------
__global__ void seg_attn_kernel(){
    int s = blockIdx.x, b = blockIdx.y;
    int h = threadIdx.x >> 6, d = threadIdx.x & 63;
    int nseg = g_nseg;
    float* outp = g_attn + ((size_t)b*NTOK + s)*E;
    if(s >= nseg){ outp[threadIdx.x] = 0.f; return; }
    int st = g_segstart[s], en = g_segstart[s+1];
    float mx = -3.402823466e38f;
    for(int n=st;n<en;n++) mx = fmaxf(mx, g_scores[n*16 + b*4 + h]);
    float ws = 0.f, acc = 0.f;
    const float* vpb = g_vp + ((size_t)b*NTOK)*E + h*64 + d;
    for(int n=st;n<en;n++){
        float wv = expf(g_scores[n*16 + b*4 + h] - mx);
        ws += wv;
        acc += wv * vpb[(size_t)n*E];
    }
    outp[h*64 + d] = acc / ws;
}

// ---------------- launch ----------------
extern "C" void kernel_launch(void* const* d_in, const int* in_sizes, int n_in,
                              void* d_out, int out_size){
    const float* video     = (const float*)d_in[0];
    const float* conv_w    = (const float*)d_in[1];
    const float* conv_b    = (const float*)d_in[2];
    const float* wq_w      = (const float*)d_in[3];
    const float* wq_b      = (const float*)d_in[4];
    const float* wk_w      = (const float*)d_in[5];
    const float* wk_b      = (const float*)d_in[6];
    const float* wv_w      = (const float*)d_in[7];
    const float* wv_b      = (const float*)d_in[8];
    const float* lnq_g     = (const float*)d_in[9];
    const float* lnq_b     = (const float*)d_in[10];
    const float* lnk_g     = (const float*)d_in[11];
    const float* lnk_b     = (const float*)d_in[12];
    const float* lnv_g     = (const float*)d_in[13];
    const float* lnv_b     = (const float*)d_in[14];
    const float* in_proj_w = (const float*)d_in[15];
    const float* in_proj_b = (const float*)d_in[16];
    const float* out_proj_w= (const float*)d_in[17];
    const float* out_proj_b= (const float*)d_in[18];
    const float* dense_w   = (const float*)d_in[19];
    const float* dense_b   = (const float*)d_in[20];
    const float* bproj_w   = (const float*)d_in[21];
    const float* bproj_b   = (const float*)d_in[22];
    const float* gq        = (const float*)d_in[23];
    const float* ent_table = (const float*)d_in[24];
    float* out = (float*)d_out;

    static int smem_set = 0;
    if(!smem_set){
        cudaFuncSetAttribute(conv_kv_kernel,   cudaFuncAttributeMaxDynamicSharedMemorySize, SMEM_BIG_FLOATS*4);
        cudaFuncSetAttribute(out_chain_kernel, cudaFuncAttributeMaxDynamicSharedMemorySize, SMEM_BIG_FLOATS*4);
        smem_set = 1;
    }

    prep_conv_kernel<<<dim3(KCONV/32, E/32), dim3(32,8)>>>(conv_w);
    prep_kernel<<<256,256>>>(wk_w, wv_w, in_proj_w, out_proj_w, dense_w, bproj_w, gq);
    qp_kernel<<<1,256>>>(gq, wq_w, wq_b, lnq_g, lnq_b, in_proj_w, in_proj_b);
    conv_kv_kernel<<<NBLK,256,SMEM_BIG_FLOATS*4>>>(video, conv_b, wk_b, wv_b, in_proj_b,
                                                   lnk_g, lnk_b, lnv_g, lnv_b);
    ent_kernel<<<NTOK,256>>>(ent_table);
    scan_kernel<<<1,1024>>>();
    seg_attn_kernel<<<dim3(NTOK,NB),256>>>();
    out_chain_kernel<<<NBLK,256,SMEM_BIG_FLOATS*4>>>(out_proj_b, dense_b, bproj_b, out);
}

// round 15
// speedup vs baseline: 1.0626x; 1.0626x over previous
#include <cuda_runtime.h>
#include <cstdint>

// ---------------- problem constants ----------------
#define E       256
#define NB      4
#define NTOK    3136            // 16 * 14 * 14
#define MTOT    (NB*NTOK)       // 12544
#define KCONV   2304            // 3 * 3 * 16 * 16
#define NCHUNK  (KCONV/16)      // 144
#define THRESH  1.5f
#define R       32              // rows per block
#define NBLK    (MTOT/R)        // 392

typedef unsigned long long ull;

// ---------------- device scratch ----------------
__device__ float g_wTconv[KCONV*E];     // conv weights transposed [k][oc]
__device__ float g_wT[7][E*E];          // 0:wk 1:wv 2:Wki 3:Wvi 4:outproj 5:dense 6:bproj  [k][n]
__device__ float g_q0add[E];
__device__ float g_vp[MTOT*E];
__device__ float g_attn[MTOT*E];
__device__ float g_bytemean[NTOK];
__device__ float g_scores[NTOK*NB*4];   // [n][b][h]
__device__ int   g_boundary[NTOK];
__device__ int   g_segstart[NTOK+2];
__device__ int   g_nseg;
__device__ float g_qp[E];

// ---------------- helpers ----------------
#define DUP(d,f)      asm("mov.b64 %0,{%1,%1};" : "=l"(d) : "f"(f))
#define FMA2(a_,b_,c_) asm("fma.rn.f32x2 %0, %1, %2, %0;" : "+l"(c_) : "l"(a_), "l"(b_))
#define SEL(v,kk) ((kk)==0?(v).x:(kk)==1?(v).y:(kk)==2?(v).z:(v).w)

__device__ __forceinline__ float2 unpack2(ull v){
    float2 r;
    r.x = __uint_as_float((unsigned)(v & 0xffffffffull));
    r.y = __uint_as_float((unsigned)(v >> 32));
    return r;
}

__device__ __forceinline__ float warpSum(float v){
    #pragma unroll
    for(int o=16;o;o>>=1) v += __shfl_xor_sync(0xffffffffu, v, o);
    return v;
}

__device__ __forceinline__ float blockReduceSum(float v, float* red){
    v = warpSum(v);
    int w = threadIdx.x >> 5, l = threadIdx.x & 31;
    if(l==0) red[w] = v;
    __syncthreads();
    if(w==0){
        float x = (l < 8) ? red[l] : 0.f;
        #pragma unroll
        for(int o=4;o;o>>=1) x += __shfl_xor_sync(0xffffffffu, x, o);
        if(l==0) red[8] = x;
    }
    __syncthreads();
    float r = red[8];
    __syncthreads();
    return r;
}

__device__ __forceinline__ float blockReduceMax(float v, float* red){
    #pragma unroll
    for(int o=16;o;o>>=1) v = fmaxf(v, __shfl_xor_sync(0xffffffffu, v, o));
    int w = threadIdx.x >> 5, l = threadIdx.x & 31;
    if(l==0) red[w] = v;
    __syncthreads();
    if(w==0){
        float x = (l < 8) ? red[l] : -3.402823466e38f;
        #pragma unroll
        for(int o=4;o;o>>=1) x = fmaxf(x, __shfl_xor_sync(0xffffffffu, x, o));
        if(l==0) red[8] = x;
    }
    __syncthreads();
    float r = red[8];
    __syncthreads();
    return r;
}

// ---------------- 16-k inner step: warp = 8 rows x 128 cols (smem B, DUP) ----------------
template<int ASTR>
__device__ __forceinline__ void mm16(const float* __restrict__ Ar, const float* __restrict__ Bcol,
                                     int kbase, ull acc[8][2]){
    ulonglong2 q = *(const ulonglong2*)&Bcol[0];
    #pragma unroll
    for(int kg=0;kg<16;kg+=4){
        float4 a[8];
        #pragma unroll
        for(int r=0;r<8;r++) a[r] = *(const float4*)&Ar[r*ASTR + kbase + kg];
        #pragma unroll
        for(int kk=0;kk<4;kk++){
            ulonglong2 qn;
            if(kg + kk < 15) qn = *(const ulonglong2*)&Bcol[(kg+kk+1)*256];
            #pragma unroll
            for(int r=0;r<8;r++){
                ull ad; DUP(ad, SEL(a[r],kk));
                FMA2(ad, q.x, acc[r][0]);
                FMA2(ad, q.y, acc[r][1]);
            }
            q = qn;
        }
    }
}

// smem-staged GEMM (conv_kv): C_block[32x256] = A_smem @ Bg, Bs2 double-buffer, 1 barrier/chunk
__device__ __forceinline__ void gemm256(const float* __restrict__ A, const float* __restrict__ Bg,
                                        float* __restrict__ Bs2, ull acc[8][2], int tid){
    int w = tid>>5, lane = tid&31;
    int wr = w & 3, chalf = w >> 2;
    const float* Ar = A + (wr*8)*256;
    int boff = chalf*128 + lane*4;
    int kl = tid>>6, c4 = (tid&63)<<2;
    #pragma unroll
    for(int i=0;i<8;i++){ acc[i][0]=0ull; acc[i][1]=0ull; }

    __syncthreads();   // A source ready; Bs2 free

    float4 pb[4];
    #pragma unroll
    for(int p=0;p<4;p++) pb[p] = *(const float4*)&Bg[(size_t)(kl + p*4)*256 + c4];
    #pragma unroll
    for(int p=0;p<4;p++) *(float4*)&Bs2[(kl + p*4)*256 + c4] = pb[p];
    #pragma unroll
    for(int p=0;p<4;p++) pb[p] = *(const float4*)&Bg[(size_t)(16 + kl + p*4)*256 + c4];
    __syncthreads();

    #pragma unroll 1
    for(int ci=0; ci<16; ci++){
        int cur = ci & 1;
        if(ci < 15){
            float* bn = Bs2 + (cur^1)*4096;
            #pragma unroll
            for(int p=0;p<4;p++) *(float4*)&bn[(kl + p*4)*256 + c4] = pb[p];
        }
        if(ci < 14){
            #pragma unroll
            for(int p=0;p<4;p++)
                pb[p] = *(const float4*)&Bg[(size_t)((ci+2)*16 + kl + p*4)*256 + c4];
        }
        mm16<256>(Ar, Bs2 + cur*4096 + boff, ci*16, acc);
        __syncthreads();
    }
}

// ---------------- LDG-direct GEMM (out_chain): B straight from global, no barriers in k ----------------
template<int ASTR>
__device__ __forceinline__ void mm16g(const float* __restrict__ Ar, const float* __restrict__ Bcol,
                                      int kbase, ull acc[8][2]){
    #pragma unroll
    for(int kg=0;kg<16;kg+=4){
        ulonglong2 q[4];
        #pragma unroll
        for(int kk=0;kk<4;kk++)
            q[kk] = *(const ulonglong2*)&Bcol[(size_t)(kbase+kg+kk)*256];
        float4 a[8];
        #pragma unroll
        for(int r=0;r<8;r++) a[r] = *(const float4*)&Ar[r*ASTR + kbase + kg];
        #pragma unroll
        for(int kk=0;kk<4;kk++){
            #pragma unroll
            for(int r=0;r<8;r++){
                ull ad; DUP(ad, SEL(a[r],kk));
                FMA2(ad, q[kk].x, acc[r][0]);
                FMA2(ad, q[kk].y, acc[r][1]);
            }
        }
    }
}

__device__ __forceinline__ void gemm256g(const float* __restrict__ A, const float* __restrict__ Bg,
                                         ull acc[8][2], int tid){
    int w = tid>>5, lane = tid&31;
    int wr = w & 3, chalf = w >> 2;
    const float* Ar = A + (wr*8)*256;
    const float* Bcol = Bg + chalf*128 + lane*4;
    #pragma unroll
    for(int i=0;i<8;i++){ acc[i][0]=0ull; acc[i][1]=0ull; }

    __syncthreads();   // A source smem ready

    #pragma unroll 1
    for(int kb=0;kb<256;kb+=16)
        mm16g<256>(Ar, Bcol, kb, acc);
}

// bias + LN row-wise (row spans 2 warps) -> smem C (stride 256)
__device__ __forceinline__ void ln_epilogue(ull acc[8][2], const float* __restrict__ bias,
        const float* __restrict__ g, const float* __restrict__ b, float* __restrict__ C,
        int wr, int chalf, int lane, float (*redS)[32][2]){
    int c0 = chalf*128 + lane*4;
    float x[8][4];
    #pragma unroll
    for(int i=0;i<8;i++){
        float2 r0 = unpack2(acc[i][0]), r1 = unpack2(acc[i][1]);
        x[i][0] = r0.x + bias[c0];   x[i][1] = r0.y + bias[c0+1];
        x[i][2] = r1.x + bias[c0+2]; x[i][3] = r1.y + bias[c0+3];
        float s = warpSum(x[i][0]+x[i][1]+x[i][2]+x[i][3]);
        if(lane==0) redS[0][wr*8+i][chalf] = s;
    }
    __syncthreads();
    float mean[8];
    #pragma unroll
    for(int i=0;i<8;i++)
        mean[i] = (redS[0][wr*8+i][0] + redS[0][wr*8+i][1]) * (1.f/256.f);
    #pragma unroll
    for(int i=0;i<8;i++){
        float vs = 0.f;
        #pragma unroll
        for(int j=0;j<4;j++){ float d = x[i][j]-mean[i]; vs += d*d; }
        vs = warpSum(vs);
        if(lane==0) redS[1][wr*8+i][chalf] = vs;
    }
    __syncthreads();
    #pragma unroll
    for(int i=0;i<8;i++){
        float var = (redS[1][wr*8+i][0] + redS[1][wr*8+i][1]) * (1.f/256.f);
        float inv = rsqrtf(var + 1e-5f);
        float4 y;
        y.x = (x[i][0]-mean[i])*inv*g[c0]   + b[c0];
        y.y = (x[i][1]-mean[i])*inv*g[c0+1] + b[c0+1];
        y.z = (x[i][2]-mean[i])*inv*g[c0+2] + b[c0+2];
        y.w = (x[i][3]-mean[i])*inv*g[c0+3] + b[c0+3];
        *(float4*)&C[(wr*8+i)*256 + c0] = y;
    }
    __syncwarp();
}

__device__ __forceinline__ void store_bias_global(ull acc[8][2], const float* __restrict__ bias,
        float* __restrict__ dst, int wr, int chalf, int lane){
    int c0 = chalf*128 + lane*4;
    #pragma unroll
    for(int i=0;i<8;i++){
        float2 r0 = unpack2(acc[i][0]), r1 = unpack2(acc[i][1]);
        float4 y = { r0.x + bias[c0], r0.y + bias[c0+1], r1.x + bias[c0+2], r1.y + bias[c0+3] };
        *(float4*)&dst[(size_t)(wr*8+i)*E + c0] = y;
    }
}

// kp epilogue: scores directly
__device__ __forceinline__ void score_epilogue(ull acc[8][2], const float* __restrict__ bias,
        int m0, int wr, int chalf, int lane){
    int c0 = chalf*128 + lane*4;
    int head = chalf*2 + (lane>>4);
    #pragma unroll
    for(int i=0;i<8;i++){
        float2 r0 = unpack2(acc[i][0]), r1 = unpack2(acc[i][1]);
        float s = (r0.x + bias[c0]  )*g_qp[c0]   + (r0.y + bias[c0+1])*g_qp[c0+1]
                + (r1.x + bias[c0+2])*g_qp[c0+2] + (r1.y + bias[c0+3])*g_qp[c0+3];
        #pragma unroll
        for(int o=8;o;o>>=1) s += __shfl_xor_sync(0xffffffffu, s, o);
        if((lane & 15) == 0){
            int m = m0 + wr*8 + i;
            int b = m / NTOK, n = m % NTOK;
            g_scores[n*16 + b*4 + head] = s;
        }
    }
}

// ---------------- fused prep: conv transpose + dense transposes + qp ----------------
// grid (72, 9), block (32, 8)
__global__ void prep_all_kernel(const float* __restrict__ conv_w,
                                const float* __restrict__ wk, const float* __restrict__ wv,
                                const float* __restrict__ ipw,
                                const float* __restrict__ outp, const float* __restrict__ dense,
                                const float* __restrict__ bproj, const float* __restrict__ gq,
                                const float* __restrict__ wq_w, const float* __restrict__ wq_b,
                                const float* __restrict__ lnq_g, const float* __restrict__ lnq_b,
                                const float* __restrict__ ipb){
    __shared__ float t[32][33];
    if(blockIdx.y < 8){
        // conv weight transpose tile
        int kk0 = blockIdx.x*32, oc0 = blockIdx.y*32;
        int tx = threadIdx.x, ty = threadIdx.y;
        #pragma unroll
        for(int p=0;p<4;p++)
            t[ty + p*8][tx] = conv_w[(size_t)(oc0 + ty + p*8)*KCONV + kk0 + tx];
        __syncthreads();
        #pragma unroll
        for(int p=0;p<4;p++)
            g_wTconv[(size_t)(kk0 + ty + p*8)*E + oc0 + tx] = t[tx][ty + p*8];
        return;
    }
    // linear part: 72 blocks x 256 threads
    int ltid = threadIdx.y*32 + threadIdx.x;
    int idx = blockIdx.x*256 + ltid;
    int stride = 72*256;
    for(int i=idx;i<E*E;i+=stride){
        int k = i >> 8, n = i & 255;
        g_wT[0][i] = wk[n*E + k];
        g_wT[1][i] = wv[n*E + k];
        g_wT[2][i] = ipw[(E   + n)*E + k];
        g_wT[3][i] = ipw[(2*E + n)*E + k];
        g_wT[4][i] = outp[n*E + k];
        g_wT[5][i] = dense[n*E + k];
        g_wT[6][i] = bproj[n*E + k];
    }
    if(idx < E) g_q0add[idx] = gq[idx];

    // qp path in block x==0 (all 256 threads cooperate)
    if(blockIdx.x == 0){
        __shared__ float red[9];
        __shared__ float q0s[E];
        __shared__ float qln[E];
        int c = ltid;
        q0s[c] = gq[c];
        __syncthreads();
        // emulate blockReduce helpers with ltid
        float y = wq_b[c];
        for(int k=0;k<E;k++) y += wq_w[c*E + k]*q0s[k];
        // block reduce sum (256 thr)
        {
            float v = warpSum(y);
            int w = c >> 5, l = c & 31;
            if(l==0) red[w] = v;
            __syncthreads();
            if(w==0){
                float x = (l < 8) ? red[l] : 0.f;
                #pragma unroll
                for(int o=4;o;o>>=1) x += __shfl_xor_sync(0xffffffffu, x, o);
                if(l==0) red[8] = x;
            }
            __syncthreads();
            float mean = red[8] * (1.f/E);
            __syncthreads();
            float dd = y - mean;
            float v2 = warpSum(dd*dd);
            if(l==0) red[w] = v2;
            __syncthreads();
            if(w==0){
                float x = (l < 8) ? red[l] : 0.f;
                #pragma unroll
                for(int o=4;o;o>>=1) x += __shfl_xor_sync(0xffffffffu, x, o);
                if(l==0) red[8] = x;
            }
            __syncthreads();
            float var = red[8] * (1.f/E);
            qln[c] = dd * rsqrtf(var + 1e-5f) * lnq_g[c] + lnq_b[c];
        }
        __syncthreads();
        float z = ipb[c];
        for(int k=0;k<E;k++) z += ipw[c*E + k]*qln[k];
        g_qp[c] = z * 0.125f;       // dh^-0.5
    }
}

// ---------------- fused conv + k/v chain (smem-staged B) ----------------
// smem floats: T[0,8192) C[8192,16384) Bs2[16384,24576)
#define SMEM_CONV_FLOATS 24576

__global__ __launch_bounds__(256,2) void conv_kv_kernel(const float* __restrict__ video,
        const float* __restrict__ conv_b,
        const float* __restrict__ wk_b, const float* __restrict__ wv_b,
        const float* __restrict__ ipb,
        const float* __restrict__ lnk_g, const float* __restrict__ lnk_b,
        const float* __restrict__ lnv_g, const float* __restrict__ lnv_b){
    extern __shared__ float sm[];
    __shared__ float redS[2][32][2];
    float* T   = sm;
    float* C   = sm + 8192;
    float* Bs2 = sm + 16384;
    float* As  = C;              // 2 x 640 ping-pong during conv
    int tid = threadIdx.x;
    int w = tid>>5, lane = tid&31;
    int wr = w & 3, chalf = w >> 2;
    int m0 = blockIdx.x*R;

    int rowA = tid >> 3, qA = tid & 7;
    int mA = m0 + rowA;
    int bA = mA / NTOK; int nA = mA % NTOK;
    int dA = nA / 196;  int hA = (nA % 196) / 14; int wA = nA % 14;
    const float* vbase = video + (size_t)(bA*3)*32*50176 + (hA*16)*224 + wA*16 + qA*2;
    int dbase = 2*dA - 1;

    int klB = tid>>6, c4B = (tid&63)<<2;
    int boff = chalf*128 + lane*4;

    ull acc[8][2];
    #pragma unroll
    for(int i=0;i<8;i++){ acc[i][0]=0ull; acc[i][1]=0ull; }

    #define GATHER_A(ci, dst) { int kb_=(ci)*16; int c_=kb_/768, rem_=kb_%768;           \
        int kd_=rem_>>8, kh_=(rem_&255)>>4; int din_=dbase+kd_;                           \
        dst = make_float2(0.f, 0.f);                                                      \
        if(din_>=0 && din_<32) dst = *(const float2*)(vbase + (size_t)(c_*32+din_)*50176 + kh_*224); }
    #define LOAD_B(ci, dst) { _Pragma("unroll")                                           \
        for(int p=0;p<4;p++) dst[p] = *(const float4*)&g_wTconv[(size_t)((ci)*16 + klB + p*4)*256 + c4B]; }

    float2 apre; float4 bpre[4];
    GATHER_A(0, apre); LOAD_B(0, bpre);
    *(float2*)&As[rowA*20 + qA*2] = apre;
    #pragma unroll
    for(int p=0;p<4;p++) *(float4*)&Bs2[(klB + p*4)*256 + c4B] = bpre[p];
    GATHER_A(1, apre); LOAD_B(1, bpre);
    __syncthreads();

    #pragma unroll 1
    for(int ci=0; ci<NCHUNK; ci++){
        int cur = ci & 1;
        if(ci < NCHUNK-1){
            float* an = As + (cur^1)*640;
            float* bn = Bs2 + (cur^1)*4096;
            *(float2*)&an[rowA*20 + qA*2] = apre;
            #pragma unroll
            for(int p=0;p<4;p++) *(float4*)&bn[(klB + p*4)*256 + c4B] = bpre[p];
        }
        if(ci < NCHUNK-2){
            GATHER_A(ci+2, apre); LOAD_B(ci+2, bpre);
        }
        mm16<20>(As + cur*640 + (wr*8)*20, Bs2 + cur*4096 + boff, 0, acc);
        __syncthreads();
    }

    // conv epilogue: bias + relu -> T; cross-warp row sums for byte path
    {
        int c0 = boff;
        #pragma unroll
        for(int i=0;i<8;i++){
            float2 r0 = unpack2(acc[i][0]), r1 = unpack2(acc[i][1]);
            float4 y = { fmaxf(r0.x + conv_b[c0],  0.f), fmaxf(r0.y + conv_b[c0+1],0.f),
                         fmaxf(r1.x + conv_b[c0+2],0.f), fmaxf(r1.y + conv_b[c0+3],0.f) };
            *(float4*)&T[(wr*8+i)*256 + c0] = y;
            float s = warpSum(y.x + y.y + y.z + y.w);
            if(lane==0) redS[0][wr*8+i][chalf] = s;
        }
        __syncthreads();
        if(m0 < NTOK && tid < 32)
            g_bytemean[m0 + tid] = (redS[0][tid][0] + redS[0][tid][1]) * (1.f/256.f);
    }

    // k path
    gemm256(T, g_wT[0], Bs2, acc, tid);
    ln_epilogue(acc, wk_b, lnk_g, lnk_b, C, wr, chalf, lane, redS);
    gemm256(C, g_wT[2], Bs2, acc, tid);
    score_epilogue(acc, ipb + E, m0, wr, chalf, lane);

    // v path
    gemm256(T, g_wT[1], Bs2, acc, tid);
    ln_epilogue(acc, wv_b, lnv_g, lnv_b, C, wr, chalf, lane, redS);
    gemm256(C, g_wT[3], Bs2, acc, tid);
    store_bias_global(acc, ipb + 2*E, g_vp + (size_t)m0*E, wr, chalf, lane);
}

// ---------------- fused out_proj -> dense -> bproj (LDG-direct B) ----------------
#define SMEM_OUT_FLOATS 16384

__global__ __launch_bounds__(256,2) void out_chain_kernel(const float* __restrict__ outp_b,
        const float* __restrict__ dense_b, const float* __restrict__ bproj_b,
        float* __restrict__ out){
    extern __shared__ float sm[];
    float* T   = sm;
    float* C   = sm + 8192;
    int tid = threadIdx.x;
    int w = tid>>5, lane = tid&31;
    int wr = w & 3, chalf = w >> 2;
    int m0 = blockIdx.x*R;
    int c0 = chalf*128 + lane*4;

    #pragma unroll
    for(int p=0;p<8;p++){
        int fid = tid + p*256;
        int r = fid>>6, c4 = (fid&63)<<2;
        *(float4*)&T[r*256 + c4] = *(const float4*)&g_attn[(size_t)(m0+r)*E + c4];
    }
    // gemm256g entry barrier orders these writes before reads

    ull acc[8][2];

    gemm256g(T, g_wT[4], acc, tid);      // attn @ out_proj
    #pragma unroll
    for(int i=0;i<8;i++){
        float2 r0 = unpack2(acc[i][0]), r1 = unpack2(acc[i][1]);
        float4 y = { r0.x + outp_b[c0], r0.y + outp_b[c0+1], r1.x + outp_b[c0+2], r1.y + outp_b[c0+3] };
        *(float4*)&C[(wr*8+i)*256 + c0] = y;
    }
    __syncwarp();

    gemm256g(C, g_wT[5], acc, tid);      // @ dense + bias + q0
    #pragma unroll
    for(int i=0;i<8;i++){
        float2 r0 = unpack2(acc[i][0]), r1 = unpack2(acc[i][1]);
        float4 y = { r0.x + dense_b[c0]   + g_q0add[c0],
                     r0.y + dense_b[c0+1] + g_q0add[c0+1],
                     r1.x + dense_b[c0+2] + g_q0add[c0+2],
                     r1.y + dense_b[c0+3] + g_q0add[c0+3] };
        *(float4*)&T[(wr*8+i)*256 + c0] = y;
    }
    __syncwarp();

    gemm256g(T, g_wT[6], acc, tid);      // @ bproj + bias, mask
    int nseg = g_nseg;
    #pragma unroll
    for(int i=0;i<8;i++){
        int m = m0 + wr*8 + i;
        int srow = m % NTOK;
        bool z = (srow >= nseg);
        float2 r0 = unpack2(acc[i][0]), r1 = unpack2(acc[i][1]);
        float4 y = { r0.x + bproj_b[c0], r0.y + bproj_b[c0+1], r1.x + bproj_b[c0+2], r1.y + bproj_b[c0+3] };
        if(z) y = make_float4(0.f,0.f,0.f,0.f);
        *(float4*)&out[(size_t)m*E + c0] = y;
    }
}

// ---------------- entropy -> boundary ----------------
__global__ void ent_kernel(const float* __restrict__ table){
    __shared__ float red[9];
    int n = blockIdx.x, c = threadIdx.x;
    float mean = g_bytemean[n];
    int byte = (int)rintf(mean * 255.f);
    byte = min(255, max(0, byte));
    float l = table[byte*256 + c];
    float mx = blockReduceMax(l, red);
    float e = expf(l - mx);
    float s = blockReduceSum(e, red);
    float p = e / s;
    float t = -p * log2f(p + 1e-9f);
    float ent = blockReduceSum(t, red);
    if(c == 0) g_boundary[n] = (ent > THRESH) ? 1 : 0;
}

// ---------------- prefix scan -> segment starts ----------------
__global__ void scan_kernel(){
    __shared__ int smi[1024];
    int tid = threadIdx.x;
    int base = tid*4;
    int v[4]; int sum = 0;
    #pragma unroll
    for(int i=0;i<4;i++){
        int idx = base + i;
        int bb = (idx < NTOK) ? g_boundary[idx] : 0;
        v[i] = sum; sum += bb;
    }
    smi[tid] = sum;
    __syncthreads();
    for(int off=1; off<1024; off<<=1){
        int t = (tid >= off) ? smi[tid-off] : 0;
        __syncthreads();
        smi[tid] += t;
        __syncthreads();
    }
    int prev = (tid > 0) ? smi[tid-1] : 0;
    if(tid == 0) g_segstart[0] = 0;
    #pragma unroll
    for(int i=0;i<4;i++){
        int idx = base + i;
        if(idx < NTOK){
            int sg = prev + v[i];
            if(g_boundary[idx]) g_segstart[sg + 1] = idx + 1;
            if(idx == NTOK-1){
                g_nseg = sg + 1;
                g_segstart[sg + 1] = NTOK;
            }
        }
    }
}

// ---------------- segment softmax-attention ----------------
__global__ void seg_attn_kernel(){
    int s = blockIdx.x, b = blockIdx.y;
    int h = threadIdx.x >> 6, d = threadIdx.x & 63;
    int nseg = g_nseg;
    float* outp = g_attn + ((size_t)b*NTOK + s)*E;
    if(s >= nseg){ outp[threadIdx.x] = 0.f; return; }
    int st = g_segstart[s], en = g_segstart[s+1];
    float mx = -3.402823466e38f;
    for(int n=st;n<en;n++) mx = fmaxf(mx, g_scores[n*16 + b*4 + h]);
    float ws = 0.f, acc = 0.f;
    const float* vpb = g_vp + ((size_t)b*NTOK)*E + h*64 + d;
    for(int n=st;n<en;n++){
        float wv = expf(g_scores[n*16 + b*4 + h] - mx);
        ws += wv;
        acc += wv * vpb[(size_t)n*E];
    }
    outp[h*64 + d] = acc / ws;
}

// ---------------- launch ----------------
extern "C" void kernel_launch(void* const* d_in, const int* in_sizes, int n_in,
                              void* d_out, int out_size){
    const float* video     = (const float*)d_in[0];
    const float* conv_w    = (const float*)d_in[1];
    const float* conv_b    = (const float*)d_in[2];
    const float* wq_w      = (const float*)d_in[3];
    const float* wq_b      = (const float*)d_in[4];
    const float* wk_w      = (const float*)d_in[5];
    const float* wk_b      = (const float*)d_in[6];
    const float* wv_w      = (const float*)d_in[7];
    const float* wv_b      = (const float*)d_in[8];
    const float* lnq_g     = (const float*)d_in[9];
    const float* lnq_b     = (const float*)d_in[10];
    const float* lnk_g     = (const float*)d_in[11];
    const float* lnk_b     = (const float*)d_in[12];
    const float* lnv_g     = (const float*)d_in[13];
    const float* lnv_b     = (const float*)d_in[14];
    const float* in_proj_w = (const float*)d_in[15];
    const float* in_proj_b = (const float*)d_in[16];
    const float* out_proj_w= (const float*)d_in[17];
    const float* out_proj_b= (const float*)d_in[18];
    const float* dense_w   = (const float*)d_in[19];
    const float* dense_b   = (const float*)d_in[20];
    const float* bproj_w   = (const float*)d_in[21];
    const float* bproj_b   = (const float*)d_in[22];
    const float* gq        = (const float*)d_in[23];
    const float* ent_table = (const float*)d_in[24];
    float* out = (float*)d_out;

    static int smem_set = 0;
    if(!smem_set){
        cudaFuncSetAttribute(conv_kv_kernel,   cudaFuncAttributeMaxDynamicSharedMemorySize, SMEM_CONV_FLOATS*4);
        cudaFuncSetAttribute(out_chain_kernel, cudaFuncAttributeMaxDynamicSharedMemorySize, SMEM_OUT_FLOATS*4);
        smem_set = 1;
    }

    prep_all_kernel<<<dim3(72,9), dim3(32,8)>>>(conv_w, wk_w, wv_w, in_proj_w,
                                                out_proj_w, dense_w, bproj_w, gq,
                                                wq_w, wq_b, lnq_g, lnq_b, in_proj_b);
    conv_kv_kernel<<<NBLK,256,SMEM_CONV_FLOATS*4>>>(video, conv_b, wk_b, wv_b, in_proj_b,
                                                    lnk_g, lnk_b, lnv_g, lnv_b);
    ent_kernel<<<NTOK,256>>>(ent_table);
    scan_kernel<<<1,1024>>>();
    seg_attn_kernel<<<dim3(NTOK,NB),256>>>();
    out_chain_kernel<<<NBLK,256,SMEM_OUT_FLOATS*4>>>(out_proj_b, dense_b, bproj_b, out);
}

// round 16
// speedup vs baseline: 1.0833x; 1.0195x over previous
#include <cuda_runtime.h>
#include <cstdint>

// ---------------- problem constants ----------------
#define E       256
#define NB      4
#define NTOK    3136            // 16 * 14 * 14
#define MTOT    (NB*NTOK)       // 12544
#define KCONV   2304            // 3 * 3 * 16 * 16
#define NCHUNK  (KCONV/16)      // 144
#define THRESH  1.5f
#define R       32              // rows per block
#define NBLK    (MTOT/R)        // 392

typedef unsigned long long ull;

// ---------------- device scratch ----------------
__device__ float g_wTconv[KCONV*E];     // conv weights transposed [k][oc]
__device__ float g_wT[7][E*E];          // 0:wk 1:wv 2:Wki 3:Wvi 4:outproj 5:dense 6:bproj  [k][n]
__device__ float g_q0add[E];
__device__ float g_vp[MTOT*E];
__device__ float g_attn[MTOT*E];
__device__ float g_bytemean[NTOK];
__device__ float g_scores[NTOK*NB*4];   // [n][b][h]
__device__ int   g_boundary[NTOK];
__device__ int   g_segstart[NTOK+2];
__device__ int   g_nseg;
__device__ float g_qp[E];

// ---------------- helpers ----------------
#define DUP(d,f)      asm("mov.b64 %0,{%1,%1};" : "=l"(d) : "f"(f))
#define FMA2(a_,b_,c_) asm("fma.rn.f32x2 %0, %1, %2, %0;" : "+l"(c_) : "l"(a_), "l"(b_))
#define SEL(v,kk) ((kk)==0?(v).x:(kk)==1?(v).y:(kk)==2?(v).z:(v).w)

__device__ __forceinline__ float2 unpack2(ull v){
    float2 r;
    r.x = __uint_as_float((unsigned)(v & 0xffffffffull));
    r.y = __uint_as_float((unsigned)(v >> 32));
    return r;
}

__device__ __forceinline__ float warpSum(float v){
    #pragma unroll
    for(int o=16;o;o>>=1) v += __shfl_xor_sync(0xffffffffu, v, o);
    return v;
}

__device__ __forceinline__ float blockReduceSum(float v, float* red){
    v = warpSum(v);
    int w = threadIdx.x >> 5, l = threadIdx.x & 31;
    if(l==0) red[w] = v;
    __syncthreads();
    if(w==0){
        float x = (l < 8) ? red[l] : 0.f;
        #pragma unroll
        for(int o=4;o;o>>=1) x += __shfl_xor_sync(0xffffffffu, x, o);
        if(l==0) red[8] = x;
    }
    __syncthreads();
    float r = red[8];
    __syncthreads();
    return r;
}

__device__ __forceinline__ float blockReduceMax(float v, float* red){
    #pragma unroll
    for(int o=16;o;o>>=1) v = fmaxf(v, __shfl_xor_sync(0xffffffffu, v, o));
    int w = threadIdx.x >> 5, l = threadIdx.x & 31;
    if(l==0) red[w] = v;
    __syncthreads();
    if(w==0){
        float x = (l < 8) ? red[l] : -3.402823466e38f;
        #pragma unroll
        for(int o=4;o;o>>=1) x = fmaxf(x, __shfl_xor_sync(0xffffffffu, x, o));
        if(l==0) red[8] = x;
    }
    __syncthreads();
    float r = red[8];
    __syncthreads();
    return r;
}

// ---------------- 16-k inner step: warp = 8 rows x 128 cols (smem B, DUP) — conv loop ----------------
template<int ASTR>
__device__ __forceinline__ void mm16(const float* __restrict__ Ar, const float* __restrict__ Bcol,
                                     int kbase, ull acc[8][2]){
    ulonglong2 q = *(const ulonglong2*)&Bcol[0];
    #pragma unroll
    for(int kg=0;kg<16;kg+=4){
        float4 a[8];
        #pragma unroll
        for(int r=0;r<8;r++) a[r] = *(const float4*)&Ar[r*ASTR + kbase + kg];
        #pragma unroll
        for(int kk=0;kk<4;kk++){
            ulonglong2 qn;
            if(kg + kk < 15) qn = *(const ulonglong2*)&Bcol[(kg+kk+1)*256];
            #pragma unroll
            for(int r=0;r<8;r++){
                ull ad; DUP(ad, SEL(a[r],kk));
                FMA2(ad, q.x, acc[r][0]);
                FMA2(ad, q.y, acc[r][1]);
            }
            q = qn;
        }
    }
}

// ---------------- LDG-direct GEMM: B straight from global, no barriers in k ----------------
template<int ASTR>
__device__ __forceinline__ void mm16g(const float* __restrict__ Ar, const float* __restrict__ Bcol,
                                      int kbase, ull acc[8][2]){
    #pragma unroll
    for(int kg=0;kg<16;kg+=4){
        ulonglong2 q[4];
        #pragma unroll
        for(int kk=0;kk<4;kk++)
            q[kk] = *(const ulonglong2*)&Bcol[(size_t)(kbase+kg+kk)*256];
        float4 a[8];
        #pragma unroll
        for(int r=0;r<8;r++) a[r] = *(const float4*)&Ar[r*ASTR + kbase + kg];
        #pragma unroll
        for(int kk=0;kk<4;kk++){
            #pragma unroll
            for(int r=0;r<8;r++){
                ull ad; DUP(ad, SEL(a[r],kk));
                FMA2(ad, q[kk].x, acc[r][0]);
                FMA2(ad, q[kk].y, acc[r][1]);
            }
        }
    }
}

__device__ __forceinline__ void gemm256g(const float* __restrict__ A, const float* __restrict__ Bg,
                                         ull acc[8][2], int tid){
    int w = tid>>5, lane = tid&31;
    int wr = w & 3, chalf = w >> 2;
    const float* Ar = A + (wr*8)*256;
    const float* Bcol = Bg + chalf*128 + lane*4;
    #pragma unroll
    for(int i=0;i<8;i++){ acc[i][0]=0ull; acc[i][1]=0ull; }

    __syncthreads();   // A source smem ready

    #pragma unroll 1
    for(int kb=0;kb<256;kb+=16)
        mm16g<256>(Ar, Bcol, kb, acc);
}

// bias + LN row-wise (row spans 2 warps) -> smem C (stride 256)
__device__ __forceinline__ void ln_epilogue(ull acc[8][2], const float* __restrict__ bias,
        const float* __restrict__ g, const float* __restrict__ b, float* __restrict__ C,
        int wr, int chalf, int lane, float (*redS)[32][2]){
    int c0 = chalf*128 + lane*4;
    float x[8][4];
    #pragma unroll
    for(int i=0;i<8;i++){
        float2 r0 = unpack2(acc[i][0]), r1 = unpack2(acc[i][1]);
        x[i][0] = r0.x + bias[c0];   x[i][1] = r0.y + bias[c0+1];
        x[i][2] = r1.x + bias[c0+2]; x[i][3] = r1.y + bias[c0+3];
        float s = warpSum(x[i][0]+x[i][1]+x[i][2]+x[i][3]);
        if(lane==0) redS[0][wr*8+i][chalf] = s;
    }
    __syncthreads();
    float mean[8];
    #pragma unroll
    for(int i=0;i<8;i++)
        mean[i] = (redS[0][wr*8+i][0] + redS[0][wr*8+i][1]) * (1.f/256.f);
    #pragma unroll
    for(int i=0;i<8;i++){
        float vs = 0.f;
        #pragma unroll
        for(int j=0;j<4;j++){ float d = x[i][j]-mean[i]; vs += d*d; }
        vs = warpSum(vs);
        if(lane==0) redS[1][wr*8+i][chalf] = vs;
    }
    __syncthreads();
    #pragma unroll
    for(int i=0;i<8;i++){
        float var = (redS[1][wr*8+i][0] + redS[1][wr*8+i][1]) * (1.f/256.f);
        float inv = rsqrtf(var + 1e-5f);
        float4 y;
        y.x = (x[i][0]-mean[i])*inv*g[c0]   + b[c0];
        y.y = (x[i][1]-mean[i])*inv*g[c0+1] + b[c0+1];
        y.z = (x[i][2]-mean[i])*inv*g[c0+2] + b[c0+2];
        y.w = (x[i][3]-mean[i])*inv*g[c0+3] + b[c0+3];
        *(float4*)&C[(wr*8+i)*256 + c0] = y;
    }
    __syncwarp();
}

__device__ __forceinline__ void store_bias_global(ull acc[8][2], const float* __restrict__ bias,
        float* __restrict__ dst, int wr, int chalf, int lane){
    int c0 = chalf*128 + lane*4;
    #pragma unroll
    for(int i=0;i<8;i++){
        float2 r0 = unpack2(acc[i][0]), r1 = unpack2(acc[i][1]);
        float4 y = { r0.x + bias[c0], r0.y + bias[c0+1], r1.x + bias[c0+2], r1.y + bias[c0+3] };
        *(float4*)&dst[(size_t)(wr*8+i)*E + c0] = y;
    }
}

// kp epilogue: scores directly
__device__ __forceinline__ void score_epilogue(ull acc[8][2], const float* __restrict__ bias,
        int m0, int wr, int chalf, int lane){
    int c0 = chalf*128 + lane*4;
    int head = chalf*2 + (lane>>4);
    #pragma unroll
    for(int i=0;i<8;i++){
        float2 r0 = unpack2(acc[i][0]), r1 = unpack2(acc[i][1]);
        float s = (r0.x + bias[c0]  )*g_qp[c0]   + (r0.y + bias[c0+1])*g_qp[c0+1]
                + (r1.x + bias[c0+2])*g_qp[c0+2] + (r1.y + bias[c0+3])*g_qp[c0+3];
        #pragma unroll
        for(int o=8;o;o>>=1) s += __shfl_xor_sync(0xffffffffu, s, o);
        if((lane & 15) == 0){
            int m = m0 + wr*8 + i;
            int b = m / NTOK, n = m % NTOK;
            g_scores[n*16 + b*4 + head] = s;
        }
    }
}

// ---------------- fused prep: conv transpose + dense transposes + qp ----------------
// grid (72, 9), block (32, 8)
__global__ void prep_all_kernel(const float* __restrict__ conv_w,
                                const float* __restrict__ wk, const float* __restrict__ wv,
                                const float* __restrict__ ipw,
                                const float* __restrict__ outp, const float* __restrict__ dense,
                                const float* __restrict__ bproj, const float* __restrict__ gq,
                                const float* __restrict__ wq_w, const float* __restrict__ wq_b,
                                const float* __restrict__ lnq_g, const float* __restrict__ lnq_b,
                                const float* __restrict__ ipb){
    __shared__ float t[32][33];
    if(blockIdx.y < 8){
        int kk0 = blockIdx.x*32, oc0 = blockIdx.y*32;
        int tx = threadIdx.x, ty = threadIdx.y;
        #pragma unroll
        for(int p=0;p<4;p++)
            t[ty + p*8][tx] = conv_w[(size_t)(oc0 + ty + p*8)*KCONV + kk0 + tx];
        __syncthreads();
        #pragma unroll
        for(int p=0;p<4;p++)
            g_wTconv[(size_t)(kk0 + ty + p*8)*E + oc0 + tx] = t[tx][ty + p*8];
        return;
    }
    int ltid = threadIdx.y*32 + threadIdx.x;
    int idx = blockIdx.x*256 + ltid;
    int stride = 72*256;
    for(int i=idx;i<E*E;i+=stride){
        int k = i >> 8, n = i & 255;
        g_wT[0][i] = wk[n*E + k];
        g_wT[1][i] = wv[n*E + k];
        g_wT[2][i] = ipw[(E   + n)*E + k];
        g_wT[3][i] = ipw[(2*E + n)*E + k];
        g_wT[4][i] = outp[n*E + k];
        g_wT[5][i] = dense[n*E + k];
        g_wT[6][i] = bproj[n*E + k];
    }
    if(idx < E) g_q0add[idx] = gq[idx];

    if(blockIdx.x == 0){
        __shared__ float red[9];
        __shared__ float q0s[E];
        __shared__ float qln[E];
        int c = ltid;
        q0s[c] = gq[c];
        __syncthreads();
        float y = wq_b[c];
        for(int k=0;k<E;k++) y += wq_w[c*E + k]*q0s[k];
        {
            float v = warpSum(y);
            int w = c >> 5, l = c & 31;
            if(l==0) red[w] = v;
            __syncthreads();
            if(w==0){
                float x = (l < 8) ? red[l] : 0.f;
                #pragma unroll
                for(int o=4;o;o>>=1) x += __shfl_xor_sync(0xffffffffu, x, o);
                if(l==0) red[8] = x;
            }
            __syncthreads();
            float mean = red[8] * (1.f/E);
            __syncthreads();
            float dd = y - mean;
            float v2 = warpSum(dd*dd);
            if(l==0) red[w] = v2;
            __syncthreads();
            if(w==0){
                float x = (l < 8) ? red[l] : 0.f;
                #pragma unroll
                for(int o=4;o;o>>=1) x += __shfl_xor_sync(0xffffffffu, x, o);
                if(l==0) red[8] = x;
            }
            __syncthreads();
            float var = red[8] * (1.f/E);
            qln[c] = dd * rsqrtf(var + 1e-5f) * lnq_g[c] + lnq_b[c];
        }
        __syncthreads();
        float z = ipb[c];
        for(int k=0;k<E;k++) z += ipw[c*E + k]*qln[k];
        g_qp[c] = z * 0.125f;       // dh^-0.5
    }
}

// ---------------- fused conv + k/v chain ----------------
// conv loop: smem-staged B (2.3MB stream); k/v GEMMs: LDG-direct B
// smem floats: T[0,8192) C[8192,16384) Bs2[16384,24576)
#define SMEM_CONV_FLOATS 24576

__global__ __launch_bounds__(256,2) void conv_kv_kernel(const float* __restrict__ video,
        const float* __restrict__ conv_b,
        const float* __restrict__ wk_b, const float* __restrict__ wv_b,
        const float* __restrict__ ipb,
        const float* __restrict__ lnk_g, const float* __restrict__ lnk_b,
        const float* __restrict__ lnv_g, const float* __restrict__ lnv_b){
    extern __shared__ float sm[];
    __shared__ float redS[2][32][2];
    float* T   = sm;
    float* C   = sm + 8192;
    float* Bs2 = sm + 16384;
    float* As  = C;              // 2 x 640 ping-pong during conv
    int tid = threadIdx.x;
    int w = tid>>5, lane = tid&31;
    int wr = w & 3, chalf = w >> 2;
    int m0 = blockIdx.x*R;

    int rowA = tid >> 3, qA = tid & 7;
    int mA = m0 + rowA;
    int bA = mA / NTOK; int nA = mA % NTOK;
    int dA = nA / 196;  int hA = (nA % 196) / 14; int wA = nA % 14;
    const float* vbase = video + (size_t)(bA*3)*32*50176 + (hA*16)*224 + wA*16 + qA*2;
    int dbase = 2*dA - 1;

    int klB = tid>>6, c4B = (tid&63)<<2;
    int boff = chalf*128 + lane*4;

    ull acc[8][2];
    #pragma unroll
    for(int i=0;i<8;i++){ acc[i][0]=0ull; acc[i][1]=0ull; }

    #define GATHER_A(ci, dst) { int kb_=(ci)*16; int c_=kb_/768, rem_=kb_%768;           \
        int kd_=rem_>>8, kh_=(rem_&255)>>4; int din_=dbase+kd_;                           \
        dst = make_float2(0.f, 0.f);                                                      \
        if(din_>=0 && din_<32) dst = *(const float2*)(vbase + (size_t)(c_*32+din_)*50176 + kh_*224); }
    #define LOAD_B(ci, dst) { _Pragma("unroll")                                           \
        for(int p=0;p<4;p++) dst[p] = *(const float4*)&g_wTconv[(size_t)((ci)*16 + klB + p*4)*256 + c4B]; }

    float2 apre; float4 bpre[4];
    GATHER_A(0, apre); LOAD_B(0, bpre);
    *(float2*)&As[rowA*20 + qA*2] = apre;
    #pragma unroll
    for(int p=0;p<4;p++) *(float4*)&Bs2[(klB + p*4)*256 + c4B] = bpre[p];
    GATHER_A(1, apre); LOAD_B(1, bpre);
    __syncthreads();

    #pragma unroll 1
    for(int ci=0; ci<NCHUNK; ci++){
        int cur = ci & 1;
        if(ci < NCHUNK-1){
            float* an = As + (cur^1)*640;
            float* bn = Bs2 + (cur^1)*4096;
            *(float2*)&an[rowA*20 + qA*2] = apre;
            #pragma unroll
            for(int p=0;p<4;p++) *(float4*)&bn[(klB + p*4)*256 + c4B] = bpre[p];
        }
        if(ci < NCHUNK-2){
            GATHER_A(ci+2, apre); LOAD_B(ci+2, bpre);
        }
        mm16<20>(As + cur*640 + (wr*8)*20, Bs2 + cur*4096 + boff, 0, acc);
        __syncthreads();
    }

    // conv epilogue: bias + relu -> T; cross-warp row sums for byte path
    {
        int c0 = boff;
        #pragma unroll
        for(int i=0;i<8;i++){
            float2 r0 = unpack2(acc[i][0]), r1 = unpack2(acc[i][1]);
            float4 y = { fmaxf(r0.x + conv_b[c0],  0.f), fmaxf(r0.y + conv_b[c0+1],0.f),
                         fmaxf(r1.x + conv_b[c0+2],0.f), fmaxf(r1.y + conv_b[c0+3],0.f) };
            *(float4*)&T[(wr*8+i)*256 + c0] = y;
            float s = warpSum(y.x + y.y + y.z + y.w);
            if(lane==0) redS[0][wr*8+i][chalf] = s;
        }
        __syncthreads();
        if(m0 < NTOK && tid < 32)
            g_bytemean[m0 + tid] = (redS[0][tid][0] + redS[0][tid][1]) * (1.f/256.f);
    }

    // k path: LDG-direct GEMMs
    gemm256g(T, g_wT[0], acc, tid);
    ln_epilogue(acc, wk_b, lnk_g, lnk_b, C, wr, chalf, lane, redS);
    gemm256g(C, g_wT[2], acc, tid);
    score_epilogue(acc, ipb + E, m0, wr, chalf, lane);

    // v path
    gemm256g(T, g_wT[1], acc, tid);
    ln_epilogue(acc, wv_b, lnv_g, lnv_b, C, wr, chalf, lane, redS);
    gemm256g(C, g_wT[3], acc, tid);
    store_bias_global(acc, ipb + 2*E, g_vp + (size_t)m0*E, wr, chalf, lane);
}

// ---------------- fused out_proj -> dense -> bproj (LDG-direct B) ----------------
#define SMEM_OUT_FLOATS 16384

__global__ __launch_bounds__(256,2) void out_chain_kernel(const float* __restrict__ outp_b,
        const float* __restrict__ dense_b, const float* __restrict__ bproj_b,
        float* __restrict__ out){
    extern __shared__ float sm[];
    float* T   = sm;
    float* C   = sm + 8192;
    int tid = threadIdx.x;
    int w = tid>>5, lane = tid&31;
    int wr = w & 3, chalf = w >> 2;
    int m0 = blockIdx.x*R;
    int c0 = chalf*128 + lane*4;

    #pragma unroll
    for(int p=0;p<8;p++){
        int fid = tid + p*256;
        int r = fid>>6, c4 = (fid&63)<<2;
        *(float4*)&T[r*256 + c4] = *(const float4*)&g_attn[(size_t)(m0+r)*E + c4];
    }
    // gemm256g entry barrier orders these writes before reads

    ull acc[8][2];

    gemm256g(T, g_wT[4], acc, tid);      // attn @ out_proj
    #pragma unroll
    for(int i=0;i<8;i++){
        float2 r0 = unpack2(acc[i][0]), r1 = unpack2(acc[i][1]);
        float4 y = { r0.x + outp_b[c0], r0.y + outp_b[c0+1], r1.x + outp_b[c0+2], r1.y + outp_b[c0+3] };
        *(float4*)&C[(wr*8+i)*256 + c0] = y;
    }
    __syncwarp();

    gemm256g(C, g_wT[5], acc, tid);      // @ dense + bias + q0
    #pragma unroll
    for(int i=0;i<8;i++){
        float2 r0 = unpack2(acc[i][0]), r1 = unpack2(acc[i][1]);
        float4 y = { r0.x + dense_b[c0]   + g_q0add[c0],
                     r0.y + dense_b[c0+1] + g_q0add[c0+1],
                     r1.x + dense_b[c0+2] + g_q0add[c0+2],
                     r1.y + dense_b[c0+3] + g_q0add[c0+3] };
        *(float4*)&T[(wr*8+i)*256 + c0] = y;
    }
    __syncwarp();

    gemm256g(T, g_wT[6], acc, tid);      // @ bproj + bias, mask
    int nseg = g_nseg;
    #pragma unroll
    for(int i=0;i<8;i++){
        int m = m0 + wr*8 + i;
        int srow = m % NTOK;
        bool z = (srow >= nseg);
        float2 r0 = unpack2(acc[i][0]), r1 = unpack2(acc[i][1]);
        float4 y = { r0.x + bproj_b[c0], r0.y + bproj_b[c0+1], r1.x + bproj_b[c0+2], r1.y + bproj_b[c0+3] };
        if(z) y = make_float4(0.f,0.f,0.f,0.f);
        *(float4*)&out[(size_t)m*E + c0] = y;
    }
}

// ---------------- entropy -> boundary ----------------
__global__ void ent_kernel(const float* __restrict__ table){
    __shared__ float red[9];
    int n = blockIdx.x, c = threadIdx.x;
    float mean = g_bytemean[n];
    int byte = (int)rintf(mean * 255.f);
    byte = min(255, max(0, byte));
    float l = table[byte*256 + c];
    float mx = blockReduceMax(l, red);
    float e = expf(l - mx);
    float s = blockReduceSum(e, red);
    float p = e / s;
    float t = -p * log2f(p + 1e-9f);
    float ent = blockReduceSum(t, red);
    if(c == 0) g_boundary[n] = (ent > THRESH) ? 1 : 0;
}

// ---------------- prefix scan -> segment starts ----------------
__global__ void scan_kernel(){
    __shared__ int smi[1024];
    int tid = threadIdx.x;
    int base = tid*4;
    int v[4]; int sum = 0;
    #pragma unroll
    for(int i=0;i<4;i++){
        int idx = base + i;
        int bb = (idx < NTOK) ? g_boundary[idx] : 0;
        v[i] = sum; sum += bb;
    }
    smi[tid] = sum;
    __syncthreads();
    for(int off=1; off<1024; off<<=1){
        int t = (tid >= off) ? smi[tid-off] : 0;
        __syncthreads();
        smi[tid] += t;
        __syncthreads();
    }
    int prev = (tid > 0) ? smi[tid-1] : 0;
    if(tid == 0) g_segstart[0] = 0;
    #pragma unroll
    for(int i=0;i<4;i++){
        int idx = base + i;
        if(idx < NTOK){
            int sg = prev + v[i];
            if(g_boundary[idx]) g_segstart[sg + 1] = idx + 1;
            if(idx == NTOK-1){
                g_nseg = sg + 1;
                g_segstart[sg + 1] = NTOK;
            }
        }
    }
}

// ---------------- segment softmax-attention ----------------
__global__ void seg_attn_kernel(){
    int s = blockIdx.x, b = blockIdx.y;
    int h = threadIdx.x >> 6, d = threadIdx.x & 63;
    int nseg = g_nseg;
    float* outp = g_attn + ((size_t)b*NTOK + s)*E;
    if(s >= nseg){ outp[threadIdx.x] = 0.f; return; }
    int st = g_segstart[s], en = g_segstart[s+1];
    float mx = -3.402823466e38f;
    for(int n=st;n<en;n++) mx = fmaxf(mx, g_scores[n*16 + b*4 + h]);
    float ws = 0.f, acc = 0.f;
    const float* vpb = g_vp + ((size_t)b*NTOK)*E + h*64 + d;
    for(int n=st;n<en;n++){
        float wv = expf(g_scores[n*16 + b*4 + h] - mx);
        ws += wv;
        acc += wv * vpb[(size_t)n*E];
    }
    outp[h*64 + d] = acc / ws;
}

// ---------------- launch ----------------
extern "C" void kernel_launch(void* const* d_in, const int* in_sizes, int n_in,
                              void* d_out, int out_size){
    const float* video     = (const float*)d_in[0];
    const float* conv_w    = (const float*)d_in[1];
    const float* conv_b    = (const float*)d_in[2];
    const float* wq_w      = (const float*)d_in[3];
    const float* wq_b      = (const float*)d_in[4];
    const float* wk_w      = (const float*)d_in[5];
    const float* wk_b      = (const float*)d_in[6];
    const float* wv_w      = (const float*)d_in[7];
    const float* wv_b      = (const float*)d_in[8];
    const float* lnq_g     = (const float*)d_in[9];
    const float* lnq_b     = (const float*)d_in[10];
    const float* lnk_g     = (const float*)d_in[11];
    const float* lnk_b     = (const float*)d_in[12];
    const float* lnv_g     = (const float*)d_in[13];
    const float* lnv_b     = (const float*)d_in[14];
    const float* in_proj_w = (const float*)d_in[15];
    const float* in_proj_b = (const float*)d_in[16];
    const float* out_proj_w= (const float*)d_in[17];
    const float* out_proj_b= (const float*)d_in[18];
    const float* dense_w   = (const float*)d_in[19];
    const float* dense_b   = (const float*)d_in[20];
    const float* bproj_w   = (const float*)d_in[21];
    const float* bproj_b   = (const float*)d_in[22];
    const float* gq        = (const float*)d_in[23];
    const float* ent_table = (const float*)d_in[24];
    float* out = (float*)d_out;

    static int smem_set = 0;
    if(!smem_set){
        cudaFuncSetAttribute(conv_kv_kernel,   cudaFuncAttributeMaxDynamicSharedMemorySize, SMEM_CONV_FLOATS*4);
        cudaFuncSetAttribute(out_chain_kernel, cudaFuncAttributeMaxDynamicSharedMemorySize, SMEM_OUT_FLOATS*4);
        smem_set = 1;
    }

    prep_all_kernel<<<dim3(72,9), dim3(32,8)>>>(conv_w, wk_w, wv_w, in_proj_w,
                                                out_proj_w, dense_w, bproj_w, gq,
                                                wq_w, wq_b, lnq_g, lnq_b, in_proj_b);
    conv_kv_kernel<<<NBLK,256,SMEM_CONV_FLOATS*4>>>(video, conv_b, wk_b, wv_b, in_proj_b,
                                                    lnk_g, lnk_b, lnv_g, lnv_b);
    ent_kernel<<<NTOK,256>>>(ent_table);
    scan_kernel<<<1,1024>>>();
    seg_attn_kernel<<<dim3(NTOK,NB),256>>>();
    out_chain_kernel<<<NBLK,256,SMEM_OUT_FLOATS*4>>>(out_proj_b, dense_b, bproj_b, out);
}

// round 17
// speedup vs baseline: 1.1018x; 1.0171x over previous
#include <cuda_runtime.h>
#include <cstdint>

// ---------------- problem constants ----------------
#define E       256
#define NB      4
#define NTOK    3136            // 16 * 14 * 14
#define MTOT    (NB*NTOK)       // 12544
#define KCONV   2304            // 3 * 3 * 16 * 16
#define NCHUNK  (KCONV/16)      // 144
#define THRESH  1.5f
#define R       32              // rows per block
#define NBLK    (MTOT/R)        // 392

typedef unsigned long long ull;

// ---------------- device scratch ----------------
__device__ float g_wTconv[KCONV*E];     // conv weights transposed [k][oc]
__device__ float g_wT[7][E*E];          // 0:wk 1:wv 2:Wki 3:Wvi 4:outproj 5:dense 6:bproj  [k][n]
__device__ float g_q0add[E];
__device__ float g_vp[MTOT*E];
__device__ float g_attn[MTOT*E];
__device__ float g_bytemean[NTOK];
__device__ float g_scores[NTOK*NB*4];   // [n][b][h]
__device__ int   g_boundary[NTOK];
__device__ int   g_segstart[NTOK+2];
__device__ int   g_nseg;
__device__ float g_qp[E];

// ---------------- helpers ----------------
#define DUP(d,f)      asm("mov.b64 %0,{%1,%1};" : "=l"(d) : "f"(f))
#define FMA2(a_,b_,c_) asm("fma.rn.f32x2 %0, %1, %2, %0;" : "+l"(c_) : "l"(a_), "l"(b_))
#define SEL(v,kk) ((kk)==0?(v).x:(kk)==1?(v).y:(kk)==2?(v).z:(v).w)

__device__ __forceinline__ float2 unpack2(ull v){
    float2 r;
    r.x = __uint_as_float((unsigned)(v & 0xffffffffull));
    r.y = __uint_as_float((unsigned)(v >> 32));
    return r;
}

__device__ __forceinline__ float warpSum(float v){
    #pragma unroll
    for(int o=16;o;o>>=1) v += __shfl_xor_sync(0xffffffffu, v, o);
    return v;
}

__device__ __forceinline__ float blockReduceSum(float v, float* red){
    v = warpSum(v);
    int w = threadIdx.x >> 5, l = threadIdx.x & 31;
    if(l==0) red[w] = v;
    __syncthreads();
    if(w==0){
        float x = (l < 8) ? red[l] : 0.f;
        #pragma unroll
        for(int o=4;o;o>>=1) x += __shfl_xor_sync(0xffffffffu, x, o);
        if(l==0) red[8] = x;
    }
    __syncthreads();
    float r = red[8];
    __syncthreads();
    return r;
}

__device__ __forceinline__ float blockReduceMax(float v, float* red){
    #pragma unroll
    for(int o=16;o;o>>=1) v = fmaxf(v, __shfl_xor_sync(0xffffffffu, v, o));
    int w = threadIdx.x >> 5, l = threadIdx.x & 31;
    if(l==0) red[w] = v;
    __syncthreads();
    if(w==0){
        float x = (l < 8) ? red[l] : -3.402823466e38f;
        #pragma unroll
        for(int o=4;o;o>>=1) x = fmaxf(x, __shfl_xor_sync(0xffffffffu, x, o));
        if(l==0) red[8] = x;
    }
    __syncthreads();
    float r = red[8];
    __syncthreads();
    return r;
}

// ---------------- LDG-direct 16-k inner step: warp = 8 rows x 128 cols ----------------
// A from smem (broadcast), B straight from global (L1/L2-resident)
template<int ASTR>
__device__ __forceinline__ void mm16g(const float* __restrict__ Ar, const float* __restrict__ Bcol,
                                      int kbase, ull acc[8][2]){
    #pragma unroll
    for(int kg=0;kg<16;kg+=4){
        ulonglong2 q[4];
        #pragma unroll
        for(int kk=0;kk<4;kk++)
            q[kk] = *(const ulonglong2*)&Bcol[(size_t)(kbase+kg+kk)*256];
        float4 a[8];
        #pragma unroll
        for(int r=0;r<8;r++) a[r] = *(const float4*)&Ar[r*ASTR + kbase + kg];
        #pragma unroll
        for(int kk=0;kk<4;kk++){
            #pragma unroll
            for(int r=0;r<8;r++){
                ull ad; DUP(ad, SEL(a[r],kk));
                FMA2(ad, q[kk].x, acc[r][0]);
                FMA2(ad, q[kk].y, acc[r][1]);
            }
        }
    }
}

__device__ __forceinline__ void gemm256g(const float* __restrict__ A, const float* __restrict__ Bg,
                                         ull acc[8][2], int tid){
    int w = tid>>5, lane = tid&31;
    int wr = w & 3, chalf = w >> 2;
    const float* Ar = A + (wr*8)*256;
    const float* Bcol = Bg + chalf*128 + lane*4;
    #pragma unroll
    for(int i=0;i<8;i++){ acc[i][0]=0ull; acc[i][1]=0ull; }

    __syncthreads();   // A source smem ready

    #pragma unroll 1
    for(int kb=0;kb<256;kb+=16)
        mm16g<256>(Ar, Bcol, kb, acc);
}

// bias + LN row-wise (row spans 2 warps) -> smem C (stride 256)
__device__ __forceinline__ void ln_epilogue(ull acc[8][2], const float* __restrict__ bias,
        const float* __restrict__ g, const float* __restrict__ b, float* __restrict__ C,
        int wr, int chalf, int lane, float (*redS)[32][2]){
    int c0 = chalf*128 + lane*4;
    float x[8][4];
    #pragma unroll
    for(int i=0;i<8;i++){
        float2 r0 = unpack2(acc[i][0]), r1 = unpack2(acc[i][1]);
        x[i][0] = r0.x + bias[c0];   x[i][1] = r0.y + bias[c0+1];
        x[i][2] = r1.x + bias[c0+2]; x[i][3] = r1.y + bias[c0+3];
        float s = warpSum(x[i][0]+x[i][1]+x[i][2]+x[i][3]);
        if(lane==0) redS[0][wr*8+i][chalf] = s;
    }
    __syncthreads();
    float mean[8];
    #pragma unroll
    for(int i=0;i<8;i++)
        mean[i] = (redS[0][wr*8+i][0] + redS[0][wr*8+i][1]) * (1.f/256.f);
    #pragma unroll
    for(int i=0;i<8;i++){
        float vs = 0.f;
        #pragma unroll
        for(int j=0;j<4;j++){ float d = x[i][j]-mean[i]; vs += d*d; }
        vs = warpSum(vs);
        if(lane==0) redS[1][wr*8+i][chalf] = vs;
    }
    __syncthreads();
    #pragma unroll
    for(int i=0;i<8;i++){
        float var = (redS[1][wr*8+i][0] + redS[1][wr*8+i][1]) * (1.f/256.f);
        float inv = rsqrtf(var + 1e-5f);
        float4 y;
        y.x = (x[i][0]-mean[i])*inv*g[c0]   + b[c0];
        y.y = (x[i][1]-mean[i])*inv*g[c0+1] + b[c0+1];
        y.z = (x[i][2]-mean[i])*inv*g[c0+2] + b[c0+2];
        y.w = (x[i][3]-mean[i])*inv*g[c0+3] + b[c0+3];
        *(float4*)&C[(wr*8+i)*256 + c0] = y;
    }
    __syncwarp();
}

__device__ __forceinline__ void store_bias_global(ull acc[8][2], const float* __restrict__ bias,
        float* __restrict__ dst, int wr, int chalf, int lane){
    int c0 = chalf*128 + lane*4;
    #pragma unroll
    for(int i=0;i<8;i++){
        float2 r0 = unpack2(acc[i][0]), r1 = unpack2(acc[i][1]);
        float4 y = { r0.x + bias[c0], r0.y + bias[c0+1], r1.x + bias[c0+2], r1.y + bias[c0+3] };
        *(float4*)&dst[(size_t)(wr*8+i)*E + c0] = y;
    }
}

// kp epilogue: scores directly
__device__ __forceinline__ void score_epilogue(ull acc[8][2], const float* __restrict__ bias,
        int m0, int wr, int chalf, int lane){
    int c0 = chalf*128 + lane*4;
    int head = chalf*2 + (lane>>4);
    #pragma unroll
    for(int i=0;i<8;i++){
        float2 r0 = unpack2(acc[i][0]), r1 = unpack2(acc[i][1]);
        float s = (r0.x + bias[c0]  )*g_qp[c0]   + (r0.y + bias[c0+1])*g_qp[c0+1]
                + (r1.x + bias[c0+2])*g_qp[c0+2] + (r1.y + bias[c0+3])*g_qp[c0+3];
        #pragma unroll
        for(int o=8;o;o>>=1) s += __shfl_xor_sync(0xffffffffu, s, o);
        if((lane & 15) == 0){
            int m = m0 + wr*8 + i;
            int b = m / NTOK, n = m % NTOK;
            g_scores[n*16 + b*4 + head] = s;
        }
    }
}

// ---------------- fused prep: conv transpose + dense transposes + qp ----------------
// grid (72, 9), block (32, 8)
__global__ void prep_all_kernel(const float* __restrict__ conv_w,
                                const float* __restrict__ wk, const float* __restrict__ wv,
                                const float* __restrict__ ipw,
                                const float* __restrict__ outp, const float* __restrict__ dense,
                                const float* __restrict__ bproj, const float* __restrict__ gq,
                                const float* __restrict__ wq_w, const float* __restrict__ wq_b,
                                const float* __restrict__ lnq_g, const float* __restrict__ lnq_b,
                                const float* __restrict__ ipb){
    __shared__ float t[32][33];
    if(blockIdx.y < 8){
        int kk0 = blockIdx.x*32, oc0 = blockIdx.y*32;
        int tx = threadIdx.x, ty = threadIdx.y;
        #pragma unroll
        for(int p=0;p<4;p++)
            t[ty + p*8][tx] = conv_w[(size_t)(oc0 + ty + p*8)*KCONV + kk0 + tx];
        __syncthreads();
        #pragma unroll
        for(int p=0;p<4;p++)
            g_wTconv[(size_t)(kk0 + ty + p*8)*E + oc0 + tx] = t[tx][ty + p*8];
        return;
    }
    int ltid = threadIdx.y*32 + threadIdx.x;
    int idx = blockIdx.x*256 + ltid;
    int stride = 72*256;
    for(int i=idx;i<E*E;i+=stride){
        int k = i >> 8, n = i & 255;
        g_wT[0][i] = wk[n*E + k];
        g_wT[1][i] = wv[n*E + k];
        g_wT[2][i] = ipw[(E   + n)*E + k];
        g_wT[3][i] = ipw[(2*E + n)*E + k];
        g_wT[4][i] = outp[n*E + k];
        g_wT[5][i] = dense[n*E + k];
        g_wT[6][i] = bproj[n*E + k];
    }
    if(idx < E) g_q0add[idx] = gq[idx];

    if(blockIdx.x == 0){
        __shared__ float red[9];
        __shared__ float q0s[E];
        __shared__ float qln[E];
        int c = ltid;
        q0s[c] = gq[c];
        __syncthreads();
        float y = wq_b[c];
        for(int k=0;k<E;k++) y += wq_w[c*E + k]*q0s[k];
        {
            float v = warpSum(y);
            int w = c >> 5, l = c & 31;
            if(l==0) red[w] = v;
            __syncthreads();
            if(w==0){
                float x = (l < 8) ? red[l] : 0.f;
                #pragma unroll
                for(int o=4;o;o>>=1) x += __shfl_xor_sync(0xffffffffu, x, o);
                if(l==0) red[8] = x;
            }
            __syncthreads();
            float mean = red[8] * (1.f/E);
            __syncthreads();
            float dd = y - mean;
            float v2 = warpSum(dd*dd);
            if(l==0) red[w] = v2;
            __syncthreads();
            if(w==0){
                float x = (l < 8) ? red[l] : 0.f;
                #pragma unroll
                for(int o=4;o;o>>=1) x += __shfl_xor_sync(0xffffffffu, x, o);
                if(l==0) red[8] = x;
            }
            __syncthreads();
            float var = red[8] * (1.f/E);
            qln[c] = dd * rsqrtf(var + 1e-5f) * lnq_g[c] + lnq_b[c];
        }
        __syncthreads();
        float z = ipb[c];
        for(int k=0;k<E;k++) z += ipw[c*E + k]*qln[k];
        g_qp[c] = z * 0.125f;       // dh^-0.5
    }
}

// ---------------- fused conv + k/v chain ----------------
// conv loop: PER-WARP A gather + LDG-direct B -> zero block barriers in the loop
// smem floats: T[0,8192) C[8192,16384) ; per-warp As (2x160) lives in C region
#define SMEM_CONV_FLOATS 16384

__global__ __launch_bounds__(256,2) void conv_kv_kernel(const float* __restrict__ video,
        const float* __restrict__ conv_b,
        const float* __restrict__ wk_b, const float* __restrict__ wv_b,
        const float* __restrict__ ipb,
        const float* __restrict__ lnk_g, const float* __restrict__ lnk_b,
        const float* __restrict__ lnv_g, const float* __restrict__ lnv_b){
    extern __shared__ float sm[];
    __shared__ float redS[2][32][2];
    float* T   = sm;
    float* C   = sm + 8192;
    int tid = threadIdx.x;
    int w = tid>>5, lane = tid&31;
    int wr = w & 3, chalf = w >> 2;
    int m0 = blockIdx.x*R;

    // per-warp gather coords: row = wr*8 + (lane>>2), kw quad = (lane&3)*4
    int rowW = lane >> 2, kqA = lane & 3;
    int mA = m0 + wr*8 + rowW;
    int bA = mA / NTOK; int nA = mA % NTOK;
    int dA = nA / 196;  int hA = (nA % 196) / 14; int wA = nA % 14;
    const float* vbase = video + (size_t)(bA*3)*32*50176 + (hA*16)*224 + wA*16 + kqA*4;
    int dbase = 2*dA - 1;

    float* myAs = C + w*320;                 // 2 x 160 floats per warp
    const float* Bconv = g_wTconv + chalf*128 + lane*4;
    int boff = chalf*128 + lane*4;

    ull acc[8][2];
    #pragma unroll
    for(int i=0;i<8;i++){ acc[i][0]=0ull; acc[i][1]=0ull; }

    #define GATHER_A4(ci, dst) { int kb_=(ci)*16; int c_=kb_/768, rem_=kb_%768;          \
        int kd_=rem_>>8, kh_=(rem_&255)>>4; int din_=dbase+kd_;                           \
        dst = make_float4(0.f,0.f,0.f,0.f);                                               \
        if(din_>=0 && din_<32) dst = *(const float4*)(vbase + (size_t)(c_*32+din_)*50176 + kh_*224); }

    float4 apre;
    GATHER_A4(0, apre);
    *(float4*)&myAs[rowW*20 + kqA*4] = apre;
    GATHER_A4(1, apre);
    __syncwarp();

    #pragma unroll 1
    for(int ci=0; ci<NCHUNK; ci++){
        int cur = ci & 1;
        if(ci < NCHUNK-1)
            *(float4*)&myAs[(cur^1)*160 + rowW*20 + kqA*4] = apre;
        if(ci < NCHUNK-2){
            GATHER_A4(ci+2, apre);
        }
        mm16g<20>(myAs + cur*160, Bconv + (size_t)ci*16*256, 0, acc);
        __syncwarp();
    }

    // conv epilogue: bias + relu -> T; cross-warp row sums for byte path
    {
        int c0 = boff;
        #pragma unroll
        for(int i=0;i<8;i++){
            float2 r0 = unpack2(acc[i][0]), r1 = unpack2(acc[i][1]);
            float4 y = { fmaxf(r0.x + conv_b[c0],  0.f), fmaxf(r0.y + conv_b[c0+1],0.f),
                         fmaxf(r1.x + conv_b[c0+2],0.f), fmaxf(r1.y + conv_b[c0+3],0.f) };
            *(float4*)&T[(wr*8+i)*256 + c0] = y;
            float s = warpSum(y.x + y.y + y.z + y.w);
            if(lane==0) redS[0][wr*8+i][chalf] = s;
        }
        __syncthreads();
        if(m0 < NTOK && tid < 32)
            g_bytemean[m0 + tid] = (redS[0][tid][0] + redS[0][tid][1]) * (1.f/256.f);
    }

    // k path: LDG-direct GEMMs
    gemm256g(T, g_wT[0], acc, tid);
    ln_epilogue(acc, wk_b, lnk_g, lnk_b, C, wr, chalf, lane, redS);
    gemm256g(C, g_wT[2], acc, tid);
    score_epilogue(acc, ipb + E, m0, wr, chalf, lane);

    // v path
    gemm256g(T, g_wT[1], acc, tid);
    ln_epilogue(acc, wv_b, lnv_g, lnv_b, C, wr, chalf, lane, redS);
    gemm256g(C, g_wT[3], acc, tid);
    store_bias_global(acc, ipb + 2*E, g_vp + (size_t)m0*E, wr, chalf, lane);
}

// ---------------- fused out_proj -> dense -> bproj (LDG-direct B) ----------------
#define SMEM_OUT_FLOATS 16384

__global__ __launch_bounds__(256,2) void out_chain_kernel(const float* __restrict__ outp_b,
        const float* __restrict__ dense_b, const float* __restrict__ bproj_b,
        float* __restrict__ out){
    extern __shared__ float sm[];
    float* T   = sm;
    float* C   = sm + 8192;
    int tid = threadIdx.x;
    int w = tid>>5, lane = tid&31;
    int wr = w & 3, chalf = w >> 2;
    int m0 = blockIdx.x*R;
    int c0 = chalf*128 + lane*4;

    #pragma unroll
    for(int p=0;p<8;p++){
        int fid = tid + p*256;
        int r = fid>>6, c4 = (fid&63)<<2;
        *(float4*)&T[r*256 + c4] = *(const float4*)&g_attn[(size_t)(m0+r)*E + c4];
    }
    // gemm256g entry barrier orders these writes before reads

    ull acc[8][2];

    gemm256g(T, g_wT[4], acc, tid);      // attn @ out_proj
    #pragma unroll
    for(int i=0;i<8;i++){
        float2 r0 = unpack2(acc[i][0]), r1 = unpack2(acc[i][1]);
        float4 y = { r0.x + outp_b[c0], r0.y + outp_b[c0+1], r1.x + outp_b[c0+2], r1.y + outp_b[c0+3] };
        *(float4*)&C[(wr*8+i)*256 + c0] = y;
    }
    __syncwarp();

    gemm256g(C, g_wT[5], acc, tid);      // @ dense + bias + q0
    #pragma unroll
    for(int i=0;i<8;i++){
        float2 r0 = unpack2(acc[i][0]), r1 = unpack2(acc[i][1]);
        float4 y = { r0.x + dense_b[c0]   + g_q0add[c0],
                     r0.y + dense_b[c0+1] + g_q0add[c0+1],
                     r1.x + dense_b[c0+2] + g_q0add[c0+2],
                     r1.y + dense_b[c0+3] + g_q0add[c0+3] };
        *(float4*)&T[(wr*8+i)*256 + c0] = y;
    }
    __syncwarp();

    gemm256g(T, g_wT[6], acc, tid);      // @ bproj + bias, mask
    int nseg = g_nseg;
    #pragma unroll
    for(int i=0;i<8;i++){
        int m = m0 + wr*8 + i;
        int srow = m % NTOK;
        bool z = (srow >= nseg);
        float2 r0 = unpack2(acc[i][0]), r1 = unpack2(acc[i][1]);
        float4 y = { r0.x + bproj_b[c0], r0.y + bproj_b[c0+1], r1.x + bproj_b[c0+2], r1.y + bproj_b[c0+3] };
        if(z) y = make_float4(0.f,0.f,0.f,0.f);
        *(float4*)&out[(size_t)m*E + c0] = y;
    }
}

// ---------------- entropy -> boundary ----------------
__global__ void ent_kernel(const float* __restrict__ table){
    __shared__ float red[9];
    int n = blockIdx.x, c = threadIdx.x;
    float mean = g_bytemean[n];
    int byte = (int)rintf(mean * 255.f);
    byte = min(255, max(0, byte));
    float l = table[byte*256 + c];
    float mx = blockReduceMax(l, red);
    float e = expf(l - mx);
    float s = blockReduceSum(e, red);
    float p = e / s;
    float t = -p * log2f(p + 1e-9f);
    float ent = blockReduceSum(t, red);
    if(c == 0) g_boundary[n] = (ent > THRESH) ? 1 : 0;
}

// ---------------- prefix scan -> segment starts ----------------
__global__ void scan_kernel(){
    __shared__ int smi[1024];
    int tid = threadIdx.x;
    int base = tid*4;
    int v[4]; int sum = 0;
    #pragma unroll
    for(int i=0;i<4;i++){
        int idx = base + i;
        int bb = (idx < NTOK) ? g_boundary[idx] : 0;
        v[i] = sum; sum += bb;
    }
    smi[tid] = sum;
    __syncthreads();
    for(int off=1; off<1024; off<<=1){
        int t = (tid >= off) ? smi[tid-off] : 0;
        __syncthreads();
        smi[tid] += t;
        __syncthreads();
    }
    int prev = (tid > 0) ? smi[tid-1] : 0;
    if(tid == 0) g_segstart[0] = 0;
    #pragma unroll
    for(int i=0;i<4;i++){
        int idx = base + i;
        if(idx < NTOK){
            int sg = prev + v[i];
            if(g_boundary[idx]) g_segstart[sg + 1] = idx + 1;
            if(idx == NTOK-1){
                g_nseg = sg + 1;
                g_segstart[sg + 1] = NTOK;
            }
        }
    }
}

// ---------------- segment softmax-attention ----------------
__global__ void seg_attn_kernel(){
    int s = blockIdx.x, b = blockIdx.y;
    int h = threadIdx.x >> 6, d = threadIdx.x & 63;
    int nseg = g_nseg;
    float* outp = g_attn + ((size_t)b*NTOK + s)*E;
    if(s >= nseg){ outp[threadIdx.x] = 0.f; return; }
    int st = g_segstart[s], en = g_segstart[s+1];
    float mx = -3.402823466e38f;
    for(int n=st;n<en;n++) mx = fmaxf(mx, g_scores[n*16 + b*4 + h]);
    float ws = 0.f, acc = 0.f;
    const float* vpb = g_vp + ((size_t)b*NTOK)*E + h*64 + d;
    for(int n=st;n<en;n++){
        float wv = expf(g_scores[n*16 + b*4 + h] - mx);
        ws += wv;
        acc += wv * vpb[(size_t)n*E];
    }
    outp[h*64 + d] = acc / ws;
}

// ---------------- launch ----------------
extern "C" void kernel_launch(void* const* d_in, const int* in_sizes, int n_in,
                              void* d_out, int out_size){
    const float* video     = (const float*)d_in[0];
    const float* conv_w    = (const float*)d_in[1];
    const float* conv_b    = (const float*)d_in[2];
    const float* wq_w      = (const float*)d_in[3];
    const float* wq_b      = (const float*)d_in[4];
    const float* wk_w      = (const float*)d_in[5];
    const float* wk_b      = (const float*)d_in[6];
    const float* wv_w      = (const float*)d_in[7];
    const float* wv_b      = (const float*)d_in[8];
    const float* lnq_g     = (const float*)d_in[9];
    const float* lnq_b     = (const float*)d_in[10];
    const float* lnk_g     = (const float*)d_in[11];
    const float* lnk_b     = (const float*)d_in[12];
    const float* lnv_g     = (const float*)d_in[13];
    const float* lnv_b     = (const float*)d_in[14];
    const float* in_proj_w = (const float*)d_in[15];
    const float* in_proj_b = (const float*)d_in[16];
    const float* out_proj_w= (const float*)d_in[17];
    const float* out_proj_b= (const float*)d_in[18];
    const float* dense_w   = (const float*)d_in[19];
    const float* dense_b   = (const float*)d_in[20];
    const float* bproj_w   = (const float*)d_in[21];
    const float* bproj_b   = (const float*)d_in[22];
    const float* gq        = (const float*)d_in[23];
    const float* ent_table = (const float*)d_in[24];
    float* out = (float*)d_out;

    static int smem_set = 0;
    if(!smem_set){
        cudaFuncSetAttribute(conv_kv_kernel,   cudaFuncAttributeMaxDynamicSharedMemorySize, SMEM_CONV_FLOATS*4);
        cudaFuncSetAttribute(out_chain_kernel, cudaFuncAttributeMaxDynamicSharedMemorySize, SMEM_OUT_FLOATS*4);
        smem_set = 1;
    }

    prep_all_kernel<<<dim3(72,9), dim3(32,8)>>>(conv_w, wk_w, wv_w, in_proj_w,
                                                out_proj_w, dense_w, bproj_w, gq,
                                                wq_w, wq_b, lnq_g, lnq_b, in_proj_b);
    conv_kv_kernel<<<NBLK,256,SMEM_CONV_FLOATS*4>>>(video, conv_b, wk_b, wv_b, in_proj_b,
                                                    lnk_g, lnk_b, lnv_g, lnv_b);
    ent_kernel<<<NTOK,256>>>(ent_table);
    scan_kernel<<<1,1024>>>();
    seg_attn_kernel<<<dim3(NTOK,NB),256>>>();
    out_chain_kernel<<<NBLK,256,SMEM_OUT_FLOATS*4>>>(out_proj_b, dense_b, bproj_b, out);
}